// round 4
// baseline (speedup 1.0000x reference)
#include <cuda_runtime.h>
#include <math.h>

#define DIM 768
#define NH 12
#define RQ 48
#define ASCALE 0.125f
#define BATCH 64

__device__ float g_qlin [BATCH*16*DIM];
__device__ float g_kTv  [DIM*DIM];
__device__ float g_kTa  [DIM*DIM];
__device__ float g_qt_v [BATCH*RQ*DIM];
__device__ float g_qt_a [BATCH*RQ*DIM];
__device__ float g_expS_v[BATCH*RQ*784];
__device__ float g_expS_a[BATCH*RQ*512];
__device__ float g_den_v[BATCH*RQ];
__device__ float g_den_a[BATCH*RQ];
__device__ float g_C_v  [BATCH*RQ*DIM];
__device__ float g_C_a  [BATCH*RQ*DIM];
__device__ float g_o_v  [BATCH*4*DIM];
__device__ float g_o_a  [BATCH*4*DIM];
__device__ float g_kfv  [BATCH*4*DIM];
__device__ float g_kfa  [BATCH*4*DIM];
__device__ float g_vfv  [BATCH*4*DIM];
__device__ float g_vfa  [BATCH*4*DIM];
__device__ float g_of   [BATCH*8*DIM];
__device__ float g_attn [BATCH*NH*8*16];

// qlin rows 0-7: xmm@fq_w, 8-11: xmm@qv_w, 12-15: xmm@qa_w
__global__ __launch_bounds__(256) void k_qlin(const float* __restrict__ xmm,
    const float* __restrict__ fq, const float* __restrict__ qv,
    const float* __restrict__ qa) {
  __shared__ float xs[16][DIM];
  int b = blockIdx.x, tid = threadIdx.x;
  const float* xb = xmm + (size_t)b*16*DIM;
  for (int i = tid; i < 16*DIM; i += 256) xs[i/DIM][i%DIM] = xb[i];
  __syncthreads();
  float acc[16][3];
#pragma unroll
  for (int r = 0; r < 16; r++) { acc[r][0]=0.f; acc[r][1]=0.f; acc[r][2]=0.f; }
  for (int k = 0; k < DIM; k++) {
    float f0=fq[(size_t)k*DIM+tid], f1=fq[(size_t)k*DIM+tid+256], f2=fq[(size_t)k*DIM+tid+512];
    float v0=qv[(size_t)k*DIM+tid], v1=qv[(size_t)k*DIM+tid+256], v2=qv[(size_t)k*DIM+tid+512];
    float a0=qa[(size_t)k*DIM+tid], a1=qa[(size_t)k*DIM+tid+256], a2=qa[(size_t)k*DIM+tid+512];
#pragma unroll
    for (int r = 0; r < 8; r++) { float x = xs[r][k];
      acc[r][0]+=x*f0; acc[r][1]+=x*f1; acc[r][2]+=x*f2; }
#pragma unroll
    for (int r = 0; r < 4; r++) { float x = xs[8+r][k];
      acc[8+r][0]+=x*v0; acc[8+r][1]+=x*v1; acc[8+r][2]+=x*v2; }
#pragma unroll
    for (int r = 0; r < 4; r++) { float x = xs[12+r][k];
      acc[12+r][0]+=x*a0; acc[12+r][1]+=x*a1; acc[12+r][2]+=x*a2; }
  }
  float* q = g_qlin + (size_t)b*16*DIM;
#pragma unroll
  for (int r = 0; r < 16; r++) {
    q[r*DIM+tid]=acc[r][0]; q[r*DIM+tid+256]=acc[r][1]; q[r*DIM+tid+512]=acc[r][2];
  }
}

// transpose K-halves of kvv_w / kva_w: g_kT[c][d] = kvw[d][c], c<768
__global__ __launch_bounds__(256) void k_tr(const float* __restrict__ kvv,
                                            const float* __restrict__ kva) {
  __shared__ float t[32][33];
  const float* src = blockIdx.z ? kva : kvv;
  float* dst = blockIdx.z ? g_kTa : g_kTv;
  int x0 = blockIdx.x*32, y0 = blockIdx.y*32;
  int tx = threadIdx.x & 31, ty = threadIdx.x >> 5;
  for (int i = 0; i < 32; i += 8)
    t[ty+i][tx] = src[(size_t)(y0+ty+i)*2*DIM + x0+tx];
  __syncthreads();
  for (int i = 0; i < 32; i += 8)
    dst[(size_t)(x0+ty+i)*DIM + y0+tx] = t[tx][ty+i];
}

// q~[b,h,n,d] = sum_e qlin[b,off+n,h*64+e] * kT[h*64+e][d]
__global__ __launch_bounds__(256) void k_qt(int which) {
  int b = blockIdx.x, h = blockIdx.y, tid = threadIdx.x;
  const float* kT = which ? g_kTa : g_kTv;
  float* qt = which ? g_qt_a : g_qt_v;
  int off = which ? 12 : 8;
  __shared__ float qs[4][64];
  qs[tid>>6][tid&63] = g_qlin[((size_t)b*16 + off + (tid>>6))*DIM + h*64 + (tid&63)];
  __syncthreads();
  float acc[4][3] = {};
  for (int e = 0; e < 64; e++) {
    const float* wr = kT + (size_t)(h*64+e)*DIM;
    float w0 = wr[tid], w1 = wr[tid+256], w2 = wr[tid+512];
    float q0=qs[0][e], q1=qs[1][e], q2=qs[2][e], q3=qs[3][e];
    acc[0][0]+=q0*w0; acc[0][1]+=q0*w1; acc[0][2]+=q0*w2;
    acc[1][0]+=q1*w0; acc[1][1]+=q1*w1; acc[1][2]+=q1*w2;
    acc[2][0]+=q2*w0; acc[2][1]+=q2*w1; acc[2][2]+=q2*w2;
    acc[3][0]+=q3*w0; acc[3][1]+=q3*w1; acc[3][2]+=q3*w2;
  }
#pragma unroll
  for (int n = 0; n < 4; n++) {
    float* o = qt + (((size_t)b*NH + h)*4 + n)*DIM;
    o[tid]=acc[n][0]; o[tid+256]=acc[n][1]; o[tid+512]=acc[n][2];
  }
}

// expS[48 x N2] = exp(SCALE * qt @ x2^T), tiled 48x64, 192 thr, 4x4/thr
__global__ __launch_bounds__(192) void k_scores(const float* __restrict__ x2,
                                                int N2, int which) {
  const float* qt = which ? g_qt_a : g_qt_v;
  float* expS = which ? g_expS_a : g_expS_v;
  __shared__ float a_s[32][52];
  __shared__ float b_s[32][68];
  int b = blockIdx.x, m0 = blockIdx.y*64, tid = threadIdx.x;
  int tr = tid % 12, tm = tid / 12;
  float acc[4][4] = {};
  const float* A = qt + (size_t)b*RQ*DIM;
  const float* X = x2 + (size_t)b*N2*DIM;
  for (int k0 = 0; k0 < DIM; k0 += 32) {
    __syncthreads();
#pragma unroll
    for (int i = 0; i < 2; i++) {
      int idx = tid + i*192;
      int r = idx >> 3, kq = idx & 7;
      float4 v = *(const float4*)(A + (size_t)r*DIM + k0 + kq*4);
      a_s[kq*4+0][r]=v.x; a_s[kq*4+1][r]=v.y; a_s[kq*4+2][r]=v.z; a_s[kq*4+3][r]=v.w;
    }
#pragma unroll
    for (int i = 0; i < 3; i++) {
      int idx = tid + i*192;
      if (idx < 512) {
        int m = idx >> 3, kq = idx & 7, gm = m0 + m;
        float4 v = make_float4(0.f,0.f,0.f,0.f);
        if (gm < N2) v = *(const float4*)(X + (size_t)gm*DIM + k0 + kq*4);
        b_s[kq*4+0][m]=v.x; b_s[kq*4+1][m]=v.y; b_s[kq*4+2][m]=v.z; b_s[kq*4+3][m]=v.w;
      }
    }
    __syncthreads();
#pragma unroll
    for (int kk = 0; kk < 32; kk++) {
      float4 av = *(const float4*)&a_s[kk][tr*4];
      float4 bv = *(const float4*)&b_s[kk][tm*4];
      const float* ap = (const float*)&av; const float* bp = (const float*)&bv;
#pragma unroll
      for (int i = 0; i < 4; i++)
#pragma unroll
        for (int j = 0; j < 4; j++) acc[i][j] += ap[i]*bp[j];
    }
  }
#pragma unroll
  for (int i = 0; i < 4; i++) {
    int r = tr*4 + i;
#pragma unroll
    for (int j = 0; j < 4; j++) {
      int m = m0 + tm*4 + j;
      if (m < N2) expS[((size_t)b*RQ + r)*N2 + m] = expf(acc[i][j]*ASCALE);
    }
  }
}

__global__ __launch_bounds__(128) void k_denom(int N2, int which) {
  const float* expS = which ? g_expS_a : g_expS_v;
  float* den = which ? g_den_a : g_den_v;
  const float* p = expS + (size_t)blockIdx.x*N2;
  float s = 0.f;
  for (int m = threadIdx.x; m < N2; m += 128) s += p[m];
#pragma unroll
  for (int o = 16; o; o >>= 1) s += __shfl_xor_sync(0xffffffffu, s, o);
  __shared__ float ws[4];
  if ((threadIdx.x & 31) == 0) ws[threadIdx.x >> 5] = s;
  __syncthreads();
  if (threadIdx.x == 0) den[blockIdx.x] = ws[0]+ws[1]+ws[2]+ws[3];
}

// C[48 x 768] = (expS @ x2)/den, tiled 48x64
__global__ __launch_bounds__(192) void k_ctx(const float* __restrict__ x2,
                                             int N2, int which) {
  const float* expS = which ? g_expS_a : g_expS_v;
  const float* den = which ? g_den_a : g_den_v;
  float* C = which ? g_C_a : g_C_v;
  __shared__ float a_s[32][52];
  __shared__ float b_s[32][68];
  int b = blockIdx.x, d0 = blockIdx.y*64, tid = threadIdx.x;
  int tr = tid % 12, td = tid / 12;
  float acc[4][4] = {};
  const float* A = expS + (size_t)b*RQ*N2;
  const float* X = x2 + (size_t)b*N2*DIM;
  for (int m0 = 0; m0 < N2; m0 += 32) {
    __syncthreads();
#pragma unroll
    for (int i = 0; i < 2; i++) {
      int idx = tid + i*192;
      int r = idx >> 3, mq = idx & 7, gm = m0 + mq*4;
      float4 v = make_float4(0.f,0.f,0.f,0.f);
      if (gm < N2) v = *(const float4*)(A + (size_t)r*N2 + gm);
      a_s[mq*4+0][r]=v.x; a_s[mq*4+1][r]=v.y; a_s[mq*4+2][r]=v.z; a_s[mq*4+3][r]=v.w;
    }
#pragma unroll
    for (int i = 0; i < 3; i++) {
      int idx = tid + i*192;
      if (idx < 512) {
        int m = idx >> 4, dq = idx & 15, gm = m0 + m;
        float4 v = make_float4(0.f,0.f,0.f,0.f);
        if (gm < N2) v = *(const float4*)(X + (size_t)gm*DIM + d0 + dq*4);
        *(float4*)&b_s[m][dq*4] = v;
      }
    }
    __syncthreads();
#pragma unroll
    for (int mm = 0; mm < 32; mm++) {
      float4 av = *(const float4*)&a_s[mm][tr*4];
      float4 bv = *(const float4*)&b_s[mm][td*4];
      const float* ap = (const float*)&av; const float* bp = (const float*)&bv;
#pragma unroll
      for (int i = 0; i < 4; i++)
#pragma unroll
        for (int j = 0; j < 4; j++) acc[i][j] += ap[i]*bp[j];
    }
  }
  float inv[4];
#pragma unroll
  for (int i = 0; i < 4; i++) inv[i] = 1.f/den[b*RQ + tr*4 + i];
#pragma unroll
  for (int i = 0; i < 4; i++)
#pragma unroll
    for (int j = 0; j < 4; j++)
      C[((size_t)b*RQ + tr*4 + i)*DIM + d0 + td*4 + j] = acc[i][j]*inv[i];
}

// o[b,n,h*64+e] = sum_d C[b,h*4+n,d] * kvw[d, 768+h*64+e]
__global__ __launch_bounds__(256) void k_ov(const float* __restrict__ kvv,
                                            const float* __restrict__ kva) {
  int b = blockIdx.x, which = blockIdx.y, tid = threadIdx.x;
  const float* C = which ? g_C_a : g_C_v;
  const float* kvw = which ? kva : kvv;
  float* o = which ? g_o_a : g_o_v;
  __shared__ float Cs[RQ][64];
  float acc[4][3] = {};
  int h0 = tid >> 6;
  for (int dd0 = 0; dd0 < DIM; dd0 += 64) {
    __syncthreads();
    for (int i = tid; i < RQ*64; i += 256)
      Cs[i>>6][i&63] = C[((size_t)b*RQ + (i>>6))*DIM + dd0 + (i&63)];
    __syncthreads();
    for (int dd = 0; dd < 64; dd++) {
      size_t wrow = (size_t)(dd0+dd)*2*DIM + DIM;
#pragma unroll
      for (int c = 0; c < 3; c++) {
        int j = tid + c*256;
        float w = kvw[wrow + j];
        int h = h0 + c*4;
#pragma unroll
        for (int n = 0; n < 4; n++) acc[n][c] += Cs[h*4+n][dd]*w;
      }
    }
  }
#pragma unroll
  for (int n = 0; n < 4; n++)
#pragma unroll
    for (int c = 0; c < 3; c++)
      o[((size_t)b*4 + n)*DIM + tid + c*256] = acc[n][c];
}

// dst[b] = src[b] (M x 768) @ W(768x768) [+bias]
template<int M>
__global__ __launch_bounds__(256) void k_mm(const float* __restrict__ src, int sbs,
    const float* __restrict__ W, const float* __restrict__ bias,
    float* __restrict__ dst, int dbs) {
  __shared__ float xs[M][DIM];
  int b = blockIdx.x, tid = threadIdx.x;
  const float* s = src + (size_t)b*sbs;
  for (int i = tid; i < M*DIM; i += 256) xs[i/DIM][i%DIM] = s[i];
  __syncthreads();
  float acc[M][3] = {};
  for (int k = 0; k < DIM; k++) {
    float w0 = W[(size_t)k*DIM+tid], w1 = W[(size_t)k*DIM+tid+256], w2 = W[(size_t)k*DIM+tid+512];
#pragma unroll
    for (int r = 0; r < M; r++) {
      float x = xs[r][k];
      acc[r][0]+=x*w0; acc[r][1]+=x*w1; acc[r][2]+=x*w2;
    }
  }
  float* d = dst + (size_t)b*dbs;
#pragma unroll
  for (int r = 0; r < M; r++)
#pragma unroll
    for (int c = 0; c < 3; c++) {
      int j = tid + c*256;
      d[r*DIM+j] = acc[r][c] + (bias ? bias[j] : 0.f);
    }
}

// final 8x16 attention, writes g_of and attn
__global__ __launch_bounds__(128) void k_fused(float* __restrict__ out, int wattn) {
  int b = blockIdx.x, tid = threadIdx.x;
  float* attn = wattn ? (out + (size_t)BATCH*16*DIM) : g_attn;
  __shared__ float qh[8][64], kh[16][64], vh[16][64], ps[8][16];
  int n_s = tid >> 4, t_s = tid & 15;
  for (int h = 0; h < NH; h++) {
    __syncthreads();
    for (int i = tid; i < 512; i += 128) {
      int n = i >> 6, e = i & 63;
      qh[n][e] = g_qlin[((size_t)b*16 + n)*DIM + h*64 + e];
    }
    for (int i = tid; i < 1024; i += 128) {
      int t = i >> 6, e = i & 63;
      kh[t][e] = g_kfv[((size_t)b*4 + (t>>2))*DIM + h*64 + e]
               + g_kfa[((size_t)b*4 + (t&3))*DIM + h*64 + e];
      vh[t][e] = g_vfv[((size_t)b*4 + (t>>2))*DIM + h*64 + e]
               + g_vfa[((size_t)b*4 + (t&3))*DIM + h*64 + e];
    }
    __syncthreads();
    float sc = 0.f;
#pragma unroll 8
    for (int e = 0; e < 64; e++) sc += qh[n_s][e]*kh[t_s][e];
    sc *= ASCALE;
    float mx = sc;
#pragma unroll
    for (int o = 8; o; o >>= 1) mx = fmaxf(mx, __shfl_xor_sync(0xffffffffu, mx, o));
    float ex = expf(sc - mx), sm = ex;
#pragma unroll
    for (int o = 8; o; o >>= 1) sm += __shfl_xor_sync(0xffffffffu, sm, o);
    float p = ex/sm;
    attn[(((size_t)b*NH + h)*8 + n_s)*16 + t_s] = p;
    ps[n_s][t_s] = p;
    __syncthreads();
    for (int i = tid; i < 512; i += 128) {
      int n = i >> 6, e = i & 63;
      float acc = 0.f;
#pragma unroll
      for (int t = 0; t < 16; t++) acc += ps[n][t]*vh[t][e];
      g_of[((size_t)b*8 + n)*DIM + h*64 + e] = acc;
    }
  }
}

extern "C" void kernel_launch(void* const* d_in, const int* in_sizes, int n_in,
                              void* d_out, int out_size) {
  const float* xmm    = (const float*)d_in[0];
  const float* xv     = (const float*)d_in[1];
  const float* xa     = (const float*)d_in[2];
  const float* qv_w   = (const float*)d_in[3];
  const float* kvv_w  = (const float*)d_in[4];
  const float* projv_w= (const float*)d_in[5];
  const float* projv_b= (const float*)d_in[6];
  const float* qa_w   = (const float*)d_in[7];
  const float* kva_w  = (const float*)d_in[8];
  const float* proja_w= (const float*)d_in[9];
  const float* proja_b= (const float*)d_in[10];
  const float* fq_w   = (const float*)d_in[11];
  const float* fk_w   = (const float*)d_in[12];
  const float* fv_w   = (const float*)d_in[13];
  const float* fproj_w= (const float*)d_in[14];
  const float* fproj_b= (const float*)d_in[15];
  float* out = (float*)d_out;
  int wattn = (out_size >= BATCH*16*DIM + BATCH*NH*8*16) ? 1 : 0;

  float *p_ov, *p_oa, *p_kfv, *p_kfa, *p_vfv, *p_vfa, *p_of;
  cudaGetSymbolAddress((void**)&p_ov, g_o_v);
  cudaGetSymbolAddress((void**)&p_oa, g_o_a);
  cudaGetSymbolAddress((void**)&p_kfv, g_kfv);
  cudaGetSymbolAddress((void**)&p_kfa, g_kfa);
  cudaGetSymbolAddress((void**)&p_vfv, g_vfv);
  cudaGetSymbolAddress((void**)&p_vfa, g_vfa);
  cudaGetSymbolAddress((void**)&p_of, g_of);

  k_qlin<<<BATCH, 256>>>(xmm, fq_w, qv_w, qa_w);
  k_tr<<<dim3(24,24,2), 256>>>(kvv_w, kva_w);
  k_qt<<<dim3(BATCH, NH), 256>>>(0);
  k_qt<<<dim3(BATCH, NH), 256>>>(1);
  k_scores<<<dim3(BATCH, 13), 192>>>(xv, 784, 0);
  k_scores<<<dim3(BATCH, 8), 192>>>(xa, 512, 1);
  k_denom<<<BATCH*RQ, 128>>>(784, 0);
  k_denom<<<BATCH*RQ, 128>>>(512, 1);
  k_ctx<<<dim3(BATCH, 12), 192>>>(xv, 784, 0);
  k_ctx<<<dim3(BATCH, 12), 192>>>(xa, 512, 1);
  k_ov<<<dim3(BATCH, 2), 256>>>(kvv_w, kva_w);
  k_mm<4><<<BATCH, 256>>>(p_ov, 4*DIM, projv_w, projv_b, out + 8*DIM, 16*DIM);
  k_mm<4><<<BATCH, 256>>>(p_oa, 4*DIM, proja_w, proja_b, out + 12*DIM, 16*DIM);
  k_mm<4><<<BATCH, 256>>>(out + 8*DIM, 16*DIM, fk_w, nullptr, p_kfv, 4*DIM);
  k_mm<4><<<BATCH, 256>>>(out + 12*DIM, 16*DIM, fk_w + DIM*DIM, nullptr, p_kfa, 4*DIM);
  k_mm<4><<<BATCH, 256>>>(out + 8*DIM, 16*DIM, fv_w, nullptr, p_vfv, 4*DIM);
  k_mm<4><<<BATCH, 256>>>(out + 12*DIM, 16*DIM, fv_w + DIM*DIM, nullptr, p_vfa, 4*DIM);
  k_fused<<<BATCH, 128>>>(out, wattn);
  k_mm<8><<<BATCH, 256>>>(p_of, 8*DIM, fproj_w, fproj_b, out, 16*DIM);
}

// round 7
// speedup vs baseline: 3.1139x; 3.1139x over previous
#include <cuda_runtime.h>
#include <math.h>

#define DIM 768
#define NH 12
#define RQ 48
#define ASCALE 0.125f
#define BATCH 64
typedef unsigned long long ull;

__device__ float g_qlin [BATCH*16*DIM];
__device__ float g_kTv  [DIM*DIM];
__device__ float g_kTa  [DIM*DIM];
__device__ float g_qt_v [BATCH*RQ*DIM];
__device__ float g_qt_a [BATCH*RQ*DIM];
__device__ float g_expS_v[BATCH*RQ*784];
__device__ float g_expS_a[BATCH*RQ*512];
__device__ float g_den_v[BATCH*RQ];
__device__ float g_den_a[BATCH*RQ];
__device__ float g_C_v  [BATCH*RQ*DIM];
__device__ float g_C_a  [BATCH*RQ*DIM];
__device__ float g_o_v  [BATCH*4*DIM];
__device__ float g_o_a  [BATCH*4*DIM];
__device__ float g_kfv  [BATCH*4*DIM];
__device__ float g_kfa  [BATCH*4*DIM];
__device__ float g_vfv  [BATCH*4*DIM];
__device__ float g_vfa  [BATCH*4*DIM];
__device__ float g_of   [BATCH*8*DIM];
__device__ float g_attn [BATCH*NH*8*16];

// ---------------- packed f32x2 helpers (sm_103a FFMA2) ----------------------
__device__ __forceinline__ ull pk2(float x) {
  ull r; unsigned u = __float_as_uint(x);
  asm("mov.b64 %0, {%1, %1};" : "=l"(r) : "r"(u)); return r;
}
__device__ __forceinline__ ull pr2(float lo, float hi) {
  ull r;
  asm("mov.b64 %0, {%1, %2};" : "=l"(r)
      : "r"(__float_as_uint(lo)), "r"(__float_as_uint(hi)));
  return r;
}
__device__ __forceinline__ void fma2(ull &d, ull a, ull b) {
  asm("fma.rn.f32x2 %0, %1, %2, %0;" : "+l"(d) : "l"(a), "l"(b));
}
__device__ __forceinline__ float2 up2(ull v) {
  unsigned lo, hi;
  asm("mov.b64 {%0, %1}, %2;" : "=r"(lo), "=r"(hi) : "l"(v));
  return make_float2(__uint_as_float(lo), __uint_as_float(hi));
}

// ---------------- generic 64x128 linear tile (K=768, W row-stride 768) ------
__device__ __forceinline__ void lin_tile(const float* __restrict__ A, int a_rpb, size_t a_bs,
    const float* __restrict__ W, const float* __restrict__ bias,
    float* __restrict__ D, int d_rpb, size_t d_bs, int r0, int c0) {
  __shared__ float a_s[32][68];
  __shared__ float b_s[32][132];
  int tid = threadIdx.x;
  int tr = tid % 16, tc = tid / 16;
  ull acc[4][4];
#pragma unroll
  for (int i = 0; i < 4; i++)
#pragma unroll
    for (int p = 0; p < 4; p++) acc[i][p] = 0ull;
  for (int k0 = 0; k0 < DIM; k0 += 32) {
    __syncthreads();
#pragma unroll
    for (int i = 0; i < 2; i++) {
      int idx = tid + i*256;
      int r = idx >> 3, kq = idx & 7;
      int gr = r0 + r;
      const float* ap = A + (size_t)(gr/a_rpb)*a_bs + (size_t)(gr%a_rpb)*DIM;
      float4 v = *(const float4*)(ap + k0 + kq*4);
      a_s[kq*4+0][r]=v.x; a_s[kq*4+1][r]=v.y; a_s[kq*4+2][r]=v.z; a_s[kq*4+3][r]=v.w;
    }
#pragma unroll
    for (int i = 0; i < 4; i++) {
      int idx = tid + i*256;
      int k = idx >> 5, cq = idx & 31;
      float4 v = *(const float4*)(W + (size_t)(k0+k)*DIM + c0 + cq*4);
      *(float4*)&b_s[k][cq*4] = v;
    }
    __syncthreads();
#pragma unroll
    for (int kk = 0; kk < 32; kk++) {
      float4 a4 = *(const float4*)&a_s[kk][tr*4];
      float4 b0 = *(const float4*)&b_s[kk][tc*4];
      float4 b1 = *(const float4*)&b_s[kk][64+tc*4];
      ull bp0=pr2(b0.x,b0.y), bp1=pr2(b0.z,b0.w), bp2=pr2(b1.x,b1.y), bp3=pr2(b1.z,b1.w);
      float av[4] = {a4.x, a4.y, a4.z, a4.w};
#pragma unroll
      for (int i = 0; i < 4; i++) {
        ull ai = pk2(av[i]);
        fma2(acc[i][0],ai,bp0); fma2(acc[i][1],ai,bp1);
        fma2(acc[i][2],ai,bp2); fma2(acc[i][3],ai,bp3);
      }
    }
  }
#pragma unroll
  for (int i = 0; i < 4; i++) {
    int gr = r0 + tr*4 + i;
    float* dp = D + (size_t)(gr/d_rpb)*d_bs + (size_t)(gr%d_rpb)*DIM;
#pragma unroll
    for (int p = 0; p < 4; p++) {
      float2 v = up2(acc[i][p]);
      int c = c0 + (p>>1)*64 + tc*4 + (p&1)*2;
      float bb0 = bias ? bias[c]   : 0.f;
      float bb1 = bias ? bias[c+1] : 0.f;
      dp[c] = v.x + bb0; dp[c+1] = v.y + bb1;
    }
  }
}

// qlin rows 0-7: xmm@fq, 8-11: xmm@qv, 12-15: xmm@qa (batched GEMM form)
__global__ __launch_bounds__(256) void k_qlin2(const float* __restrict__ xmm,
    const float* __restrict__ fq, const float* __restrict__ qv,
    const float* __restrict__ qa) {
  int z = blockIdx.z;
  if (z > 0 && blockIdx.x >= 4) return;
  const float* W = (z==0) ? fq : (z==1 ? qv : qa);
  int off = (z==0) ? 0 : (z==1 ? 8 : 12);
  int rpb = (z==0) ? 8 : 4;
  lin_tile(xmm + (size_t)off*DIM, rpb, (size_t)16*DIM, W, nullptr,
           g_qlin + (size_t)off*DIM, rpb, (size_t)16*DIM,
           blockIdx.x*64, blockIdx.y*128);
}

// transpose K-halves of kvv_w / kva_w: g_kT[c][d] = kvw[d][c], c<768
__global__ __launch_bounds__(256) void k_tr(const float* __restrict__ kvv,
                                            const float* __restrict__ kva) {
  __shared__ float t[32][33];
  const float* src = blockIdx.z ? kva : kvv;
  float* dst = blockIdx.z ? g_kTa : g_kTv;
  int x0 = blockIdx.x*32, y0 = blockIdx.y*32;
  int tx = threadIdx.x & 31, ty = threadIdx.x >> 5;
  for (int i = 0; i < 32; i += 8)
    t[ty+i][tx] = src[(size_t)(y0+ty+i)*2*DIM + x0+tx];
  __syncthreads();
  for (int i = 0; i < 32; i += 8)
    dst[(size_t)(x0+ty+i)*DIM + y0+tx] = t[tx][ty+i];
}

// q~[b,h,n,d] = sum_e qlin[b,off+n,h*64+e] * kT[h*64+e][d]; kT slice read once
__global__ __launch_bounds__(256) void k_qt2() {
  int h = blockIdx.x, d0 = blockIdx.y*128, which = blockIdx.z, tid = threadIdx.x;
  const float* kT = which ? g_kTa : g_kTv;
  float* qt = which ? g_qt_a : g_qt_v;
  int off = which ? 12 : 8;
  __shared__ float kts[64][129];
  __shared__ float qsh[4][64];
#pragma unroll
  for (int i = 0; i < 8; i++) {
    int idx = tid + i*256;
    int e = idx >> 5, cq = idx & 31;
    float4 v = *(const float4*)(kT + (size_t)(h*64+e)*DIM + d0 + cq*4);
    kts[e][cq*4]=v.x; kts[e][cq*4+1]=v.y; kts[e][cq*4+2]=v.z; kts[e][cq*4+3]=v.w;
  }
  int col = tid & 127, rp = tid >> 7;
  for (int b = 0; b < BATCH; b++) {
    __syncthreads();
    { int n = (tid >> 6) & 3, e = tid & 63;
      qsh[n][e] = g_qlin[((size_t)b*16 + off + n)*DIM + h*64 + e]; }
    __syncthreads();
    float a0 = 0.f, a1 = 0.f;
#pragma unroll
    for (int e = 0; e < 64; e++) {
      float w = kts[e][col];
      a0 += qsh[rp*2][e]*w; a1 += qsh[rp*2+1][e]*w;
    }
    qt[(((size_t)b*NH + h)*4 + rp*2  )*DIM + d0 + col] = a0;
    qt[(((size_t)b*NH + h)*4 + rp*2+1)*DIM + d0 + col] = a1;
  }
}

// expS[48 x N2] = exp(SCALE * qt @ x2^T): 48x128 tile, 96 thr, 8x8/thr, FFMA2
__global__ __launch_bounds__(96) void k_scores2(const float* __restrict__ xv,
                                                const float* __restrict__ xa) {
  int b = blockIdx.x, y = blockIdx.y, tid = threadIdx.x;
  int which = (y >= 7);
  int m0 = (which ? (y-7) : y) * 128;
  int N2 = which ? 512 : 784;
  const float* A = (which ? g_qt_a : g_qt_v) + (size_t)b*RQ*DIM;
  const float* X = (which ? xa : xv) + (size_t)b*N2*DIM;
  float* expS = (which ? g_expS_a : g_expS_v) + (size_t)b*RQ*N2;
  __shared__ float a_s[32][52];
  __shared__ float b_s[32][132];
  int tr = tid % 6, tc = tid / 6;
  ull acc[8][4];
#pragma unroll
  for (int i = 0; i < 8; i++)
#pragma unroll
    for (int p = 0; p < 4; p++) acc[i][p] = 0ull;
  for (int k0 = 0; k0 < DIM; k0 += 32) {
    __syncthreads();
#pragma unroll
    for (int i = 0; i < 4; i++) {
      int idx = tid + i*96;
      int r = idx >> 3, kq = idx & 7;
      float4 v = *(const float4*)(A + (size_t)r*DIM + k0 + kq*4);
      a_s[kq*4+0][r]=v.x; a_s[kq*4+1][r]=v.y; a_s[kq*4+2][r]=v.z; a_s[kq*4+3][r]=v.w;
    }
#pragma unroll
    for (int i = 0; i < 11; i++) {
      int idx = tid + i*96;
      if (idx < 1024) {
        int m = idx >> 3, kq = idx & 7, gm = m0 + m;
        float4 v = make_float4(0.f,0.f,0.f,0.f);
        if (gm < N2) v = *(const float4*)(X + (size_t)gm*DIM + k0 + kq*4);
        b_s[kq*4+0][m]=v.x; b_s[kq*4+1][m]=v.y; b_s[kq*4+2][m]=v.z; b_s[kq*4+3][m]=v.w;
      }
    }
    __syncthreads();
#pragma unroll
    for (int kk = 0; kk < 32; kk++) {
      float4 a0 = *(const float4*)&a_s[kk][tr*8];
      float4 a1 = *(const float4*)&a_s[kk][tr*8+4];
      float4 b0 = *(const float4*)&b_s[kk][tc*4];
      float4 b1 = *(const float4*)&b_s[kk][64+tc*4];
      ull bp0=pr2(b0.x,b0.y), bp1=pr2(b0.z,b0.w), bp2=pr2(b1.x,b1.y), bp3=pr2(b1.z,b1.w);
      float av[8] = {a0.x,a0.y,a0.z,a0.w,a1.x,a1.y,a1.z,a1.w};
#pragma unroll
      for (int i = 0; i < 8; i++) {
        ull ai = pk2(av[i]);
        fma2(acc[i][0],ai,bp0); fma2(acc[i][1],ai,bp1);
        fma2(acc[i][2],ai,bp2); fma2(acc[i][3],ai,bp3);
      }
    }
  }
#pragma unroll
  for (int i = 0; i < 8; i++) {
    float* row = expS + (size_t)(tr*8+i)*N2;
#pragma unroll
    for (int p = 0; p < 4; p++) {
      float2 v = up2(acc[i][p]);
      int c = m0 + (p>>1)*64 + tc*4 + (p&1)*2;
      if (c   < N2) row[c]   = expf(v.x*ASCALE);
      if (c+1 < N2) row[c+1] = expf(v.y*ASCALE);
    }
  }
}

__global__ __launch_bounds__(128) void k_denom2() {
  int which = blockIdx.y;
  int N2 = which ? 512 : 784;
  const float* expS = which ? g_expS_a : g_expS_v;
  float* den = which ? g_den_a : g_den_v;
  const float* p = expS + (size_t)blockIdx.x*N2;
  float s = 0.f;
  for (int m = threadIdx.x; m < N2; m += 128) s += p[m];
#pragma unroll
  for (int o = 16; o; o >>= 1) s += __shfl_xor_sync(0xffffffffu, s, o);
  __shared__ float ws[4];
  if ((threadIdx.x & 31) == 0) ws[threadIdx.x >> 5] = s;
  __syncthreads();
  if (threadIdx.x == 0) den[blockIdx.x] = ws[0]+ws[1]+ws[2]+ws[3];
}

// C[48 x 768] = (expS @ x2)/den: 48x128 tile, 96 thr, 8x8/thr, FFMA2
__global__ __launch_bounds__(96) void k_ctx2(const float* __restrict__ xv,
                                             const float* __restrict__ xa) {
  int b = blockIdx.x, d0 = blockIdx.y*128, which = blockIdx.z, tid = threadIdx.x;
  int N2 = which ? 512 : 784;
  const float* A = (which ? g_expS_a : g_expS_v) + (size_t)b*RQ*N2;
  const float* X = (which ? xa : xv) + (size_t)b*N2*DIM;
  const float* den = (which ? g_den_a : g_den_v) + b*RQ;
  float* C = (which ? g_C_a : g_C_v) + (size_t)b*RQ*DIM;
  __shared__ float a_s[32][52];
  __shared__ float b_s[32][132];
  int tr = tid % 6, tc = tid / 6;
  ull acc[8][4];
#pragma unroll
  for (int i = 0; i < 8; i++)
#pragma unroll
    for (int p = 0; p < 4; p++) acc[i][p] = 0ull;
  int nk = (N2 + 31) / 32;
  for (int t = 0; t < nk; t++) {
    int k0 = t*32;
    __syncthreads();
#pragma unroll
    for (int i = 0; i < 4; i++) {
      int idx = tid + i*96;
      int r = idx >> 3, mq = idx & 7, gm = k0 + mq*4;
      float4 v = make_float4(0.f,0.f,0.f,0.f);
      if (gm < N2) v = *(const float4*)(A + (size_t)r*N2 + gm);
      a_s[mq*4+0][r]=v.x; a_s[mq*4+1][r]=v.y; a_s[mq*4+2][r]=v.z; a_s[mq*4+3][r]=v.w;
    }
#pragma unroll
    for (int i = 0; i < 11; i++) {
      int idx = tid + i*96;
      if (idx < 1024) {
        int m = idx >> 5, dq = idx & 31, gm = k0 + m;
        float4 v = make_float4(0.f,0.f,0.f,0.f);
        if (gm < N2) v = *(const float4*)(X + (size_t)gm*DIM + d0 + dq*4);
        *(float4*)&b_s[m][dq*4] = v;
      }
    }
    __syncthreads();
#pragma unroll
    for (int kk = 0; kk < 32; kk++) {
      float4 a0 = *(const float4*)&a_s[kk][tr*8];
      float4 a1 = *(const float4*)&a_s[kk][tr*8+4];
      float4 b0 = *(const float4*)&b_s[kk][tc*4];
      float4 b1 = *(const float4*)&b_s[kk][64+tc*4];
      ull bp0=pr2(b0.x,b0.y), bp1=pr2(b0.z,b0.w), bp2=pr2(b1.x,b1.y), bp3=pr2(b1.z,b1.w);
      float av[8] = {a0.x,a0.y,a0.z,a0.w,a1.x,a1.y,a1.z,a1.w};
#pragma unroll
      for (int i = 0; i < 8; i++) {
        ull ai = pk2(av[i]);
        fma2(acc[i][0],ai,bp0); fma2(acc[i][1],ai,bp1);
        fma2(acc[i][2],ai,bp2); fma2(acc[i][3],ai,bp3);
      }
    }
  }
#pragma unroll
  for (int i = 0; i < 8; i++) {
    int r = tr*8 + i;
    float inv = 1.f / den[r];
    float* crow = C + (size_t)r*DIM;
#pragma unroll
    for (int p = 0; p < 4; p++) {
      float2 v = up2(acc[i][p]);
      int c = d0 + (p>>1)*64 + tc*4 + (p&1)*2;
      crow[c] = v.x*inv; crow[c+1] = v.y*inv;
    }
  }
}

// o[b,n,h*64+c] = sum_d C[b,h*4+n,d] * kvw[d, 768+h*64+c]; per-(h,bgroup) tiles
__global__ __launch_bounds__(256) void k_ov2(const float* __restrict__ kvv,
                                             const float* __restrict__ kva) {
  int h = blockIdx.x, b0 = blockIdx.y*16, which = blockIdx.z, tid = threadIdx.x;
  const float* C = which ? g_C_a : g_C_v;
  const float* kvw = which ? kva : kvv;
  float* o = which ? g_o_a : g_o_v;
  __shared__ float a_s[32][68];
  __shared__ float b_s[32][68];
  int tr = tid % 16, tc = tid / 16;
  ull acc[4][2];
#pragma unroll
  for (int i = 0; i < 4; i++) { acc[i][0]=0ull; acc[i][1]=0ull; }
  for (int k0 = 0; k0 < DIM; k0 += 32) {
    __syncthreads();
#pragma unroll
    for (int i = 0; i < 2; i++) {
      int idx = tid + i*256;
      int r = idx >> 3, kq = idx & 7;
      const float* ap = C + ((size_t)(b0 + (r>>2))*RQ + h*4 + (r&3))*DIM;
      float4 v = *(const float4*)(ap + k0 + kq*4);
      a_s[kq*4+0][r]=v.x; a_s[kq*4+1][r]=v.y; a_s[kq*4+2][r]=v.z; a_s[kq*4+3][r]=v.w;
    }
#pragma unroll
    for (int i = 0; i < 2; i++) {
      int idx = tid + i*256;
      int k = idx >> 4, cq = idx & 15;
      float4 v = *(const float4*)(kvw + (size_t)(k0+k)*2*DIM + DIM + h*64 + cq*4);
      *(float4*)&b_s[k][cq*4] = v;
    }
    __syncthreads();
#pragma unroll
    for (int kk = 0; kk < 32; kk++) {
      float4 a4 = *(const float4*)&a_s[kk][tr*4];
      float4 b4 = *(const float4*)&b_s[kk][tc*4];
      ull bp0 = pr2(b4.x,b4.y), bp1 = pr2(b4.z,b4.w);
      float av[4] = {a4.x, a4.y, a4.z, a4.w};
#pragma unroll
      for (int i = 0; i < 4; i++) {
        ull ai = pk2(av[i]);
        fma2(acc[i][0],ai,bp0); fma2(acc[i][1],ai,bp1);
      }
    }
  }
#pragma unroll
  for (int i = 0; i < 4; i++) {
    int r = tr*4 + i;
    float* dp = o + ((size_t)(b0 + (r>>2))*4 + (r&3))*DIM + h*64;
#pragma unroll
    for (int p = 0; p < 2; p++) {
      float2 v = up2(acc[i][p]);
      int c = tc*4 + p*2;
      dp[c] = v.x; dp[c+1] = v.y;
    }
  }
}

__global__ __launch_bounds__(256) void k_lin_proj(const float* __restrict__ pv_w,
    const float* __restrict__ pv_b, const float* __restrict__ pa_w,
    const float* __restrict__ pa_b, float* __restrict__ out) {
  int z = blockIdx.z;
  lin_tile(z ? g_o_a : g_o_v, 4, (size_t)4*DIM, z ? pa_w : pv_w, z ? pa_b : pv_b,
           out + (size_t)(8 + 4*z)*DIM, 4, (size_t)16*DIM,
           blockIdx.x*64, blockIdx.y*128);
}

__global__ __launch_bounds__(256) void k_lin_kv(const float* __restrict__ fk,
    const float* __restrict__ fv, const float* __restrict__ out) {
  int z = blockIdx.z, half = z & 1;
  const float* W = (z < 2 ? fk : fv) + (size_t)half*DIM*DIM;
  float* D = (z==0) ? g_kfv : (z==1) ? g_kfa : (z==2) ? g_vfv : g_vfa;
  lin_tile(out + (size_t)(8 + 4*half)*DIM, 4, (size_t)16*DIM, W, nullptr,
           D, 4, (size_t)4*DIM, blockIdx.x*64, blockIdx.y*128);
}

__global__ __launch_bounds__(256) void k_lin_fproj(const float* __restrict__ W,
    const float* __restrict__ bias, float* __restrict__ out) {
  lin_tile(g_of, 8, (size_t)8*DIM, W, bias, out, 8, (size_t)16*DIM,
           blockIdx.x*64, blockIdx.y*128);
}

// final 8x16 attention, writes g_of and attn
__global__ __launch_bounds__(128) void k_fused(float* __restrict__ out, int wattn) {
  int b = blockIdx.x, tid = threadIdx.x;
  float* attn = wattn ? (out + (size_t)BATCH*16*DIM) : g_attn;
  __shared__ float qh[8][64], kh[16][64], vh[16][64], ps[8][16];
  int n_s = tid >> 4, t_s = tid & 15;
  for (int h = 0; h < NH; h++) {
    __syncthreads();
    for (int i = tid; i < 512; i += 128) {
      int n = i >> 6, e = i & 63;
      qh[n][e] = g_qlin[((size_t)b*16 + n)*DIM + h*64 + e];
    }
    for (int i = tid; i < 1024; i += 128) {
      int t = i >> 6, e = i & 63;
      kh[t][e] = g_kfv[((size_t)b*4 + (t>>2))*DIM + h*64 + e]
               + g_kfa[((size_t)b*4 + (t&3))*DIM + h*64 + e];
      vh[t][e] = g_vfv[((size_t)b*4 + (t>>2))*DIM + h*64 + e]
               + g_vfa[((size_t)b*4 + (t&3))*DIM + h*64 + e];
    }
    __syncthreads();
    float sc = 0.f;
#pragma unroll 8
    for (int e = 0; e < 64; e++) sc += qh[n_s][e]*kh[t_s][e];
    sc *= ASCALE;
    float mx = sc;
#pragma unroll
    for (int o = 8; o; o >>= 1) mx = fmaxf(mx, __shfl_xor_sync(0xffffffffu, mx, o));
    float ex = expf(sc - mx), sm = ex;
#pragma unroll
    for (int o = 8; o; o >>= 1) sm += __shfl_xor_sync(0xffffffffu, sm, o);
    float p = ex/sm;
    attn[(((size_t)b*NH + h)*8 + n_s)*16 + t_s] = p;
    ps[n_s][t_s] = p;
    __syncthreads();
    for (int i = tid; i < 512; i += 128) {
      int n = i >> 6, e = i & 63;
      float acc = 0.f;
#pragma unroll
      for (int t = 0; t < 16; t++) acc += ps[n][t]*vh[t][e];
      g_of[((size_t)b*8 + n)*DIM + h*64 + e] = acc;
    }
  }
}

extern "C" void kernel_launch(void* const* d_in, const int* in_sizes, int n_in,
                              void* d_out, int out_size) {
  const float* xmm    = (const float*)d_in[0];
  const float* xv     = (const float*)d_in[1];
  const float* xa     = (const float*)d_in[2];
  const float* qv_w   = (const float*)d_in[3];
  const float* kvv_w  = (const float*)d_in[4];
  const float* projv_w= (const float*)d_in[5];
  const float* projv_b= (const float*)d_in[6];
  const float* qa_w   = (const float*)d_in[7];
  const float* kva_w  = (const float*)d_in[8];
  const float* proja_w= (const float*)d_in[9];
  const float* proja_b= (const float*)d_in[10];
  const float* fq_w   = (const float*)d_in[11];
  const float* fk_w   = (const float*)d_in[12];
  const float* fv_w   = (const float*)d_in[13];
  const float* fproj_w= (const float*)d_in[14];
  const float* fproj_b= (const float*)d_in[15];
  float* out = (float*)d_out;
  int wattn = (out_size >= BATCH*16*DIM + BATCH*NH*8*16) ? 1 : 0;

  k_qlin2<<<dim3(8,6,3), 256>>>(xmm, fq_w, qv_w, qa_w);
  k_tr<<<dim3(24,24,2), 256>>>(kvv_w, kva_w);
  k_qt2<<<dim3(12,6,2), 256>>>();
  k_scores2<<<dim3(64,11), 96>>>(xv, xa);
  k_denom2<<<dim3(BATCH*RQ,2), 128>>>();
  k_ctx2<<<dim3(64,6,2), 96>>>(xv, xa);
  k_ov2<<<dim3(12,4,2), 256>>>(kvv_w, kva_w);
  k_lin_proj<<<dim3(4,6,2), 256>>>(projv_w, projv_b, proja_w, proja_b, out);
  k_lin_kv<<<dim3(4,6,4), 256>>>(fk_w, fv_w, out);
  k_fused<<<BATCH, 128>>>(out, wattn);
  k_lin_fproj<<<dim3(8,6), 256>>>(fproj_w, fproj_b, out);
}

// round 8
// speedup vs baseline: 3.3488x; 1.0754x over previous
#include <cuda_runtime.h>
#include <math.h>

#define DIM 768
#define NH 12
#define RQ 48
#define ASCALE 0.125f
#define BATCH 64
typedef unsigned long long ull;

__device__ float g_qlin [BATCH*16*DIM];
__device__ float g_kTv  [DIM*DIM];
__device__ float g_kTa  [DIM*DIM];
__device__ float g_qt_v [BATCH*RQ*DIM];
__device__ float g_qt_a [BATCH*RQ*DIM];
__device__ float g_expS_v[BATCH*RQ*784];
__device__ float g_expS_a[BATCH*RQ*512];
__device__ float g_den_v[BATCH*RQ];
__device__ float g_den_a[BATCH*RQ];
__device__ float g_C_v  [BATCH*RQ*DIM];
__device__ float g_C_a  [BATCH*RQ*DIM];
__device__ float g_o_v  [BATCH*4*DIM];
__device__ float g_o_a  [BATCH*4*DIM];
__device__ float g_kfv  [BATCH*4*DIM];
__device__ float g_kfa  [BATCH*4*DIM];
__device__ float g_vfv  [BATCH*4*DIM];
__device__ float g_vfa  [BATCH*4*DIM];
__device__ float g_of   [BATCH*8*DIM];
__device__ float g_attn [BATCH*NH*8*16];

// ---------------- packed f32x2 helpers (sm_103a FFMA2) ----------------------
__device__ __forceinline__ ull pk2(float x) {
  ull r; unsigned u = __float_as_uint(x);
  asm("mov.b64 %0, {%1, %1};" : "=l"(r) : "r"(u)); return r;
}
__device__ __forceinline__ void fma2(ull &d, ull a, ull b) {
  asm("fma.rn.f32x2 %0, %1, %2, %0;" : "+l"(d) : "l"(a), "l"(b));
}
__device__ __forceinline__ float2 up2(ull v) {
  unsigned lo, hi;
  asm("mov.b64 {%0, %1}, %2;" : "=r"(lo), "=r"(hi) : "l"(v));
  return make_float2(__uint_as_float(lo), __uint_as_float(hi));
}

// ---------------- generic 64x128 linear tile (K=768), reg-prefetched --------
__device__ __forceinline__ void lin_tile(const float* __restrict__ A, int a_rpb, size_t a_bs,
    const float* __restrict__ W, const float* __restrict__ bias,
    float* __restrict__ D, int d_rpb, size_t d_bs, int r0, int c0) {
  __shared__ float a_s[32][68];
  __shared__ float b_s[32][132];
  int tid = threadIdx.x;
  int tr = tid % 16, tc = tid / 16;
  ull acc[4][4];
#pragma unroll
  for (int i = 0; i < 4; i++)
#pragma unroll
    for (int p = 0; p < 4; p++) acc[i][p] = 0ull;
  float4 pa[2], pw[4];
  int ar[2]; const float* aptr[2];
#pragma unroll
  for (int i = 0; i < 2; i++) {
    int idx = tid + i*256;
    ar[i] = idx & 7;
    int gr = r0 + (idx >> 3);
    aptr[i] = A + (size_t)(gr/a_rpb)*a_bs + (size_t)(gr%a_rpb)*DIM;
  }
#pragma unroll
  for (int i = 0; i < 2; i++) pa[i] = *(const float4*)(aptr[i] + ar[i]*4);
#pragma unroll
  for (int i = 0; i < 4; i++) {
    int idx = tid + i*256;
    pw[i] = *(const float4*)(W + (size_t)(idx>>5)*DIM + c0 + (idx&31)*4);
  }
  for (int t = 0; t < 24; t++) {
#pragma unroll
    for (int i = 0; i < 2; i++) {
      int idx = tid + i*256;
      int r = idx >> 3, kq = idx & 7;
      a_s[kq*4+0][r]=pa[i].x; a_s[kq*4+1][r]=pa[i].y;
      a_s[kq*4+2][r]=pa[i].z; a_s[kq*4+3][r]=pa[i].w;
    }
#pragma unroll
    for (int i = 0; i < 4; i++) {
      int idx = tid + i*256;
      *(float4*)&b_s[idx>>5][(idx&31)*4] = pw[i];
    }
    __syncthreads();
    if (t < 23) {
      int k0 = (t+1)*32;
#pragma unroll
      for (int i = 0; i < 2; i++) pa[i] = *(const float4*)(aptr[i] + k0 + ar[i]*4);
#pragma unroll
      for (int i = 0; i < 4; i++) {
        int idx = tid + i*256;
        pw[i] = *(const float4*)(W + (size_t)(k0 + (idx>>5))*DIM + c0 + (idx&31)*4);
      }
    }
#pragma unroll
    for (int kk = 0; kk < 32; kk++) {
      float4 a4 = *(const float4*)&a_s[kk][tr*4];
      const ull* q0 = (const ull*)&b_s[kk][tc*4];
      const ull* q1 = (const ull*)&b_s[kk][64+tc*4];
      ull bp0=q0[0], bp1=q0[1], bp2=q1[0], bp3=q1[1];
      float av[4] = {a4.x, a4.y, a4.z, a4.w};
#pragma unroll
      for (int i = 0; i < 4; i++) {
        ull ai = pk2(av[i]);
        fma2(acc[i][0],ai,bp0); fma2(acc[i][1],ai,bp1);
        fma2(acc[i][2],ai,bp2); fma2(acc[i][3],ai,bp3);
      }
    }
    __syncthreads();
  }
#pragma unroll
  for (int i = 0; i < 4; i++) {
    int gr = r0 + tr*4 + i;
    float* dp = D + (size_t)(gr/d_rpb)*d_bs + (size_t)(gr%d_rpb)*DIM;
#pragma unroll
    for (int p = 0; p < 4; p++) {
      float2 v = up2(acc[i][p]);
      int c = c0 + (p>>1)*64 + tc*4 + (p&1)*2;
      float bb0 = bias ? bias[c]   : 0.f;
      float bb1 = bias ? bias[c+1] : 0.f;
      dp[c] = v.x + bb0; dp[c+1] = v.y + bb1;
    }
  }
}

// qlin rows 0-7: xmm@fq, 8-11: xmm@qv, 12-15: xmm@qa
__global__ __launch_bounds__(256) void k_qlin2(const float* __restrict__ xmm,
    const float* __restrict__ fq, const float* __restrict__ qv,
    const float* __restrict__ qa) {
  int z = blockIdx.z;
  if (z > 0 && blockIdx.x >= 4) return;
  const float* W = (z==0) ? fq : (z==1 ? qv : qa);
  int off = (z==0) ? 0 : (z==1 ? 8 : 12);
  int rpb = (z==0) ? 8 : 4;
  lin_tile(xmm + (size_t)off*DIM, rpb, (size_t)16*DIM, W, nullptr,
           g_qlin + (size_t)off*DIM, rpb, (size_t)16*DIM,
           blockIdx.x*64, blockIdx.y*128);
}

// transpose K-halves of kvv_w / kva_w
__global__ __launch_bounds__(256) void k_tr(const float* __restrict__ kvv,
                                            const float* __restrict__ kva) {
  __shared__ float t[32][33];
  const float* src = blockIdx.z ? kva : kvv;
  float* dst = blockIdx.z ? g_kTa : g_kTv;
  int x0 = blockIdx.x*32, y0 = blockIdx.y*32;
  int tx = threadIdx.x & 31, ty = threadIdx.x >> 5;
  for (int i = 0; i < 32; i += 8)
    t[ty+i][tx] = src[(size_t)(y0+ty+i)*2*DIM + x0+tx];
  __syncthreads();
  for (int i = 0; i < 32; i += 8)
    dst[(size_t)(x0+ty+i)*DIM + y0+tx] = t[tx][ty+i];
}

// q~ = (qlin rows) @ kT, pre-scaled by ASCALE
__global__ __launch_bounds__(256) void k_qt2() {
  int h = blockIdx.x, d0 = blockIdx.y*128, which = blockIdx.z, tid = threadIdx.x;
  const float* kT = which ? g_kTa : g_kTv;
  float* qt = which ? g_qt_a : g_qt_v;
  int off = which ? 12 : 8;
  __shared__ float kts[64][129];
  __shared__ float qsh[4][64];
#pragma unroll
  for (int i = 0; i < 8; i++) {
    int idx = tid + i*256;
    int e = idx >> 5, cq = idx & 31;
    float4 v = *(const float4*)(kT + (size_t)(h*64+e)*DIM + d0 + cq*4);
    kts[e][cq*4]=v.x; kts[e][cq*4+1]=v.y; kts[e][cq*4+2]=v.z; kts[e][cq*4+3]=v.w;
  }
  int col = tid & 127, rp = tid >> 7;
  for (int b = 0; b < BATCH; b++) {
    __syncthreads();
    { int n = (tid >> 6) & 3, e = tid & 63;
      qsh[n][e] = g_qlin[((size_t)b*16 + off + n)*DIM + h*64 + e]; }
    __syncthreads();
    float a0 = 0.f, a1 = 0.f;
#pragma unroll
    for (int e = 0; e < 64; e++) {
      float w = kts[e][col];
      a0 += qsh[rp*2][e]*w; a1 += qsh[rp*2+1][e]*w;
    }
    qt[(((size_t)b*NH + h)*4 + rp*2  )*DIM + d0 + col] = a0*ASCALE;
    qt[(((size_t)b*NH + h)*4 + rp*2+1)*DIM + d0 + col] = a1*ASCALE;
  }
}

// expS = exp(qt @ x2^T) + fused row-sum (atomicAdd into den); prefetched
__global__ __launch_bounds__(96) void k_scores3(const float* __restrict__ xv,
                                                const float* __restrict__ xa) {
  int b = blockIdx.x, y = blockIdx.y, tid = threadIdx.x;
  int which = (y >= 7);
  int m0 = (which ? (y-7) : y) * 128;
  int N2 = which ? 512 : 784;
  const float* A = (which ? g_qt_a : g_qt_v) + (size_t)b*RQ*DIM;
  const float* X = (which ? xa : xv) + (size_t)b*N2*DIM;
  float* expS = (which ? g_expS_a : g_expS_v) + (size_t)b*RQ*N2;
  float* den  = (which ? g_den_a : g_den_v) + b*RQ;
  __shared__ float a_s[32][52];
  __shared__ float b_s[32][132];
  int tr = tid % 6, tc = tid / 6;
  ull acc[8][4];
#pragma unroll
  for (int i = 0; i < 8; i++)
#pragma unroll
    for (int p = 0; p < 4; p++) acc[i][p] = 0ull;
  float4 pa[4], pb[11];
#pragma unroll
  for (int i = 0; i < 4; i++) {
    int idx = tid + i*96;
    pa[i] = *(const float4*)(A + (size_t)(idx>>3)*DIM + (idx&7)*4);
  }
#pragma unroll
  for (int i = 0; i < 11; i++) {
    int idx = tid + i*96;
    if (idx < 1024) {
      int gm = m0 + (idx >> 3);
      pb[i] = make_float4(0.f,0.f,0.f,0.f);
      if (gm < N2) pb[i] = *(const float4*)(X + (size_t)gm*DIM + (idx&7)*4);
    }
  }
  for (int t = 0; t < 24; t++) {
#pragma unroll
    for (int i = 0; i < 4; i++) {
      int idx = tid + i*96;
      int r = idx >> 3, kq = idx & 7;
      a_s[kq*4+0][r]=pa[i].x; a_s[kq*4+1][r]=pa[i].y;
      a_s[kq*4+2][r]=pa[i].z; a_s[kq*4+3][r]=pa[i].w;
    }
#pragma unroll
    for (int i = 0; i < 11; i++) {
      int idx = tid + i*96;
      if (idx < 1024) {
        int m = idx >> 3, kq = idx & 7;
        b_s[kq*4+0][m]=pb[i].x; b_s[kq*4+1][m]=pb[i].y;
        b_s[kq*4+2][m]=pb[i].z; b_s[kq*4+3][m]=pb[i].w;
      }
    }
    __syncthreads();
    if (t < 23) {
      int k0 = (t+1)*32;
#pragma unroll
      for (int i = 0; i < 4; i++) {
        int idx = tid + i*96;
        pa[i] = *(const float4*)(A + (size_t)(idx>>3)*DIM + k0 + (idx&7)*4);
      }
#pragma unroll
      for (int i = 0; i < 11; i++) {
        int idx = tid + i*96;
        if (idx < 1024) {
          int gm = m0 + (idx >> 3);
          pb[i] = make_float4(0.f,0.f,0.f,0.f);
          if (gm < N2) pb[i] = *(const float4*)(X + (size_t)gm*DIM + k0 + (idx&7)*4);
        }
      }
    }
#pragma unroll
    for (int kk = 0; kk < 32; kk++) {
      float4 a0 = *(const float4*)&a_s[kk][tr*8];
      float4 a1 = *(const float4*)&a_s[kk][tr*8+4];
      const ull* q0 = (const ull*)&b_s[kk][tc*4];
      const ull* q1 = (const ull*)&b_s[kk][64+tc*4];
      ull bp0=q0[0], bp1=q0[1], bp2=q1[0], bp3=q1[1];
      float av[8] = {a0.x,a0.y,a0.z,a0.w,a1.x,a1.y,a1.z,a1.w};
#pragma unroll
      for (int i = 0; i < 8; i++) {
        ull ai = pk2(av[i]);
        fma2(acc[i][0],ai,bp0); fma2(acc[i][1],ai,bp1);
        fma2(acc[i][2],ai,bp2); fma2(acc[i][3],ai,bp3);
      }
    }
    __syncthreads();
  }
  // epilogue: exp + store + per-thread row partial sums
  float rs[8];
#pragma unroll
  for (int i = 0; i < 8; i++) {
    float* row = expS + (size_t)(tr*8+i)*N2;
    float s = 0.f;
#pragma unroll
    for (int p = 0; p < 4; p++) {
      float2 v = up2(acc[i][p]);
      int c = m0 + (p>>1)*64 + tc*4 + (p&1)*2;
      if (c < N2)   { float e = __expf(v.x); row[c]   = e; s += e; }
      if (c+1 < N2) { float e = __expf(v.y); row[c+1] = e; s += e; }
    }
    rs[i] = s;
  }
  float* red = &b_s[0][0];   // 48*16 floats, smem reuse (post-sync)
#pragma unroll
  for (int i = 0; i < 8; i++) red[(tr*8+i)*16 + tc] = rs[i];
  __syncthreads();
  if (tid < 48) {
    float s = 0.f;
#pragma unroll
    for (int j = 0; j < 16; j++) s += red[tid*16 + j];
    atomicAdd(&den[tid], s);
  }
}

// C = (expS @ x2)/den, prefetched
__global__ __launch_bounds__(96) void k_ctx3(const float* __restrict__ xv,
                                             const float* __restrict__ xa) {
  int b = blockIdx.x, d0 = blockIdx.y*128, which = blockIdx.z, tid = threadIdx.x;
  int N2 = which ? 512 : 784;
  const float* A = (which ? g_expS_a : g_expS_v) + (size_t)b*RQ*N2;
  const float* X = (which ? xa : xv) + (size_t)b*N2*DIM;
  const float* den = (which ? g_den_a : g_den_v) + b*RQ;
  float* C = (which ? g_C_a : g_C_v) + (size_t)b*RQ*DIM;
  __shared__ float a_s[32][52];
  __shared__ float b_s[32][132];
  int tr = tid % 6, tc = tid / 6;
  ull acc[8][4];
#pragma unroll
  for (int i = 0; i < 8; i++)
#pragma unroll
    for (int p = 0; p < 4; p++) acc[i][p] = 0ull;
  int nk = (N2 + 31) / 32;
  float4 pa[4], pb[11];
#pragma unroll
  for (int i = 0; i < 4; i++) {
    int idx = tid + i*96;
    int gm = (idx & 7)*4;
    pa[i] = make_float4(0.f,0.f,0.f,0.f);
    if (gm < N2) pa[i] = *(const float4*)(A + (size_t)(idx>>3)*N2 + gm);
  }
#pragma unroll
  for (int i = 0; i < 11; i++) {
    int idx = tid + i*96;
    if (idx < 1024) {
      int gm = idx >> 5;
      pb[i] = make_float4(0.f,0.f,0.f,0.f);
      if (gm < N2) pb[i] = *(const float4*)(X + (size_t)gm*DIM + d0 + (idx&31)*4);
    }
  }
  for (int t = 0; t < nk; t++) {
#pragma unroll
    for (int i = 0; i < 4; i++) {
      int idx = tid + i*96;
      int r = idx >> 3, mq = idx & 7;
      a_s[mq*4+0][r]=pa[i].x; a_s[mq*4+1][r]=pa[i].y;
      a_s[mq*4+2][r]=pa[i].z; a_s[mq*4+3][r]=pa[i].w;
    }
#pragma unroll
    for (int i = 0; i < 11; i++) {
      int idx = tid + i*96;
      if (idx < 1024) *(float4*)&b_s[idx>>5][(idx&31)*4] = pb[i];
    }
    __syncthreads();
    if (t+1 < nk) {
      int k0 = (t+1)*32;
#pragma unroll
      for (int i = 0; i < 4; i++) {
        int idx = tid + i*96;
        int gm = k0 + (idx & 7)*4;
        pa[i] = make_float4(0.f,0.f,0.f,0.f);
        if (gm < N2) pa[i] = *(const float4*)(A + (size_t)(idx>>3)*N2 + gm);
      }
#pragma unroll
      for (int i = 0; i < 11; i++) {
        int idx = tid + i*96;
        if (idx < 1024) {
          int gm = k0 + (idx >> 5);
          pb[i] = make_float4(0.f,0.f,0.f,0.f);
          if (gm < N2) pb[i] = *(const float4*)(X + (size_t)gm*DIM + d0 + (idx&31)*4);
        }
      }
    }
#pragma unroll
    for (int mm = 0; mm < 32; mm++) {
      float4 a0 = *(const float4*)&a_s[mm][tr*8];
      float4 a1 = *(const float4*)&a_s[mm][tr*8+4];
      const ull* q0 = (const ull*)&b_s[mm][tc*4];
      const ull* q1 = (const ull*)&b_s[mm][64+tc*4];
      ull bp0=q0[0], bp1=q0[1], bp2=q1[0], bp3=q1[1];
      float av[8] = {a0.x,a0.y,a0.z,a0.w,a1.x,a1.y,a1.z,a1.w};
#pragma unroll
      for (int i = 0; i < 8; i++) {
        ull ai = pk2(av[i]);
        fma2(acc[i][0],ai,bp0); fma2(acc[i][1],ai,bp1);
        fma2(acc[i][2],ai,bp2); fma2(acc[i][3],ai,bp3);
      }
    }
    __syncthreads();
  }
#pragma unroll
  for (int i = 0; i < 8; i++) {
    int r = tr*8 + i;
    float inv = 1.f / den[r];
    float* crow = C + (size_t)r*DIM;
#pragma unroll
    for (int p = 0; p < 4; p++) {
      float2 v = up2(acc[i][p]);
      int c = d0 + (p>>1)*64 + tc*4 + (p&1)*2;
      crow[c] = v.x*inv; crow[c+1] = v.y*inv;
    }
  }
}

// o = C @ Wv-half (per-head)
__global__ __launch_bounds__(256) void k_ov2(const float* __restrict__ kvv,
                                             const float* __restrict__ kva) {
  int h = blockIdx.x, b0 = blockIdx.y*16, which = blockIdx.z, tid = threadIdx.x;
  const float* C = which ? g_C_a : g_C_v;
  const float* kvw = which ? kva : kvv;
  float* o = which ? g_o_a : g_o_v;
  __shared__ float a_s[32][68];
  __shared__ float b_s[32][68];
  int tr = tid % 16, tc = tid / 16;
  ull acc[4][2];
#pragma unroll
  for (int i = 0; i < 4; i++) { acc[i][0]=0ull; acc[i][1]=0ull; }
  for (int k0 = 0; k0 < DIM; k0 += 32) {
    __syncthreads();
#pragma unroll
    for (int i = 0; i < 2; i++) {
      int idx = tid + i*256;
      int r = idx >> 3, kq = idx & 7;
      const float* ap = C + ((size_t)(b0 + (r>>2))*RQ + h*4 + (r&3))*DIM;
      float4 v = *(const float4*)(ap + k0 + kq*4);
      a_s[kq*4+0][r]=v.x; a_s[kq*4+1][r]=v.y; a_s[kq*4+2][r]=v.z; a_s[kq*4+3][r]=v.w;
    }
#pragma unroll
    for (int i = 0; i < 2; i++) {
      int idx = tid + i*256;
      int k = idx >> 4, cq = idx & 15;
      float4 v = *(const float4*)(kvw + (size_t)(k0+k)*2*DIM + DIM + h*64 + cq*4);
      *(float4*)&b_s[k][cq*4] = v;
    }
    __syncthreads();
#pragma unroll
    for (int kk = 0; kk < 32; kk++) {
      float4 a4 = *(const float4*)&a_s[kk][tr*4];
      const ull* q0 = (const ull*)&b_s[kk][tc*4];
      ull bp0 = q0[0], bp1 = q0[1];
      float av[4] = {a4.x, a4.y, a4.z, a4.w};
#pragma unroll
      for (int i = 0; i < 4; i++) {
        ull ai = pk2(av[i]);
        fma2(acc[i][0],ai,bp0); fma2(acc[i][1],ai,bp1);
      }
    }
  }
#pragma unroll
  for (int i = 0; i < 4; i++) {
    int r = tr*4 + i;
    float* dp = o + ((size_t)(b0 + (r>>2))*4 + (r&3))*DIM + h*64;
#pragma unroll
    for (int p = 0; p < 2; p++) {
      float2 v = up2(acc[i][p]);
      int c = tc*4 + p*2;
      dp[c] = v.x; dp[c+1] = v.y;
    }
  }
}

__global__ __launch_bounds__(256) void k_lin_proj(const float* __restrict__ pv_w,
    const float* __restrict__ pv_b, const float* __restrict__ pa_w,
    const float* __restrict__ pa_b, float* __restrict__ out) {
  int z = blockIdx.z;
  lin_tile(z ? g_o_a : g_o_v, 4, (size_t)4*DIM, z ? pa_w : pv_w, z ? pa_b : pv_b,
           out + (size_t)(8 + 4*z)*DIM, 4, (size_t)16*DIM,
           blockIdx.x*64, blockIdx.y*128);
}

__global__ __launch_bounds__(256) void k_lin_kv(const float* __restrict__ fk,
    const float* __restrict__ fv, const float* __restrict__ out) {
  int z = blockIdx.z, half = z & 1;
  const float* W = (z < 2 ? fk : fv) + (size_t)half*DIM*DIM;
  float* D = (z==0) ? g_kfv : (z==1) ? g_kfa : (z==2) ? g_vfv : g_vfa;
  lin_tile(out + (size_t)(8 + 4*half)*DIM, 4, (size_t)16*DIM, W, nullptr,
           D, 4, (size_t)4*DIM, blockIdx.x*64, blockIdx.y*128);
}

__global__ __launch_bounds__(256) void k_lin_fproj(const float* __restrict__ W,
    const float* __restrict__ bias, float* __restrict__ out) {
  lin_tile(g_of, 8, (size_t)8*DIM, W, bias, out, 8, (size_t)16*DIM,
           blockIdx.x*64, blockIdx.y*128);
}

// final 8x16 attention
__global__ __launch_bounds__(128) void k_fused(float* __restrict__ out, int wattn) {
  int b = blockIdx.x, tid = threadIdx.x;
  float* attn = wattn ? (out + (size_t)BATCH*16*DIM) : g_attn;
  __shared__ float qh[8][64], kh[16][64], vh[16][64], ps[8][16];
  int n_s = tid >> 4, t_s = tid & 15;
  for (int h = 0; h < NH; h++) {
    __syncthreads();
    for (int i = tid; i < 512; i += 128) {
      int n = i >> 6, e = i & 63;
      qh[n][e] = g_qlin[((size_t)b*16 + n)*DIM + h*64 + e];
    }
    for (int i = tid; i < 1024; i += 128) {
      int t = i >> 6, e = i & 63;
      kh[t][e] = g_kfv[((size_t)b*4 + (t>>2))*DIM + h*64 + e]
               + g_kfa[((size_t)b*4 + (t&3))*DIM + h*64 + e];
      vh[t][e] = g_vfv[((size_t)b*4 + (t>>2))*DIM + h*64 + e]
               + g_vfa[((size_t)b*4 + (t&3))*DIM + h*64 + e];
    }
    __syncthreads();
    float sc = 0.f;
#pragma unroll 8
    for (int e = 0; e < 64; e++) sc += qh[n_s][e]*kh[t_s][e];
    sc *= ASCALE;
    float mx = sc;
#pragma unroll
    for (int o = 8; o; o >>= 1) mx = fmaxf(mx, __shfl_xor_sync(0xffffffffu, mx, o));
    float ex = expf(sc - mx), sm = ex;
#pragma unroll
    for (int o = 8; o; o >>= 1) sm += __shfl_xor_sync(0xffffffffu, sm, o);
    float p = ex/sm;
    attn[(((size_t)b*NH + h)*8 + n_s)*16 + t_s] = p;
    ps[n_s][t_s] = p;
    __syncthreads();
    for (int i = tid; i < 512; i += 128) {
      int n = i >> 6, e = i & 63;
      float acc = 0.f;
#pragma unroll
      for (int t = 0; t < 16; t++) acc += ps[n][t]*vh[t][e];
      g_of[((size_t)b*8 + n)*DIM + h*64 + e] = acc;
    }
  }
}

extern "C" void kernel_launch(void* const* d_in, const int* in_sizes, int n_in,
                              void* d_out, int out_size) {
  const float* xmm    = (const float*)d_in[0];
  const float* xv     = (const float*)d_in[1];
  const float* xa     = (const float*)d_in[2];
  const float* qv_w   = (const float*)d_in[3];
  const float* kvv_w  = (const float*)d_in[4];
  const float* projv_w= (const float*)d_in[5];
  const float* projv_b= (const float*)d_in[6];
  const float* qa_w   = (const float*)d_in[7];
  const float* kva_w  = (const float*)d_in[8];
  const float* proja_w= (const float*)d_in[9];
  const float* proja_b= (const float*)d_in[10];
  const float* fq_w   = (const float*)d_in[11];
  const float* fk_w   = (const float*)d_in[12];
  const float* fv_w   = (const float*)d_in[13];
  const float* fproj_w= (const float*)d_in[14];
  const float* fproj_b= (const float*)d_in[15];
  float* out = (float*)d_out;
  int wattn = (out_size >= BATCH*16*DIM + BATCH*NH*8*16) ? 1 : 0;

  void *p_denv, *p_dena;
  cudaGetSymbolAddress(&p_denv, g_den_v);
  cudaGetSymbolAddress(&p_dena, g_den_a);
  cudaMemsetAsync(p_denv, 0, BATCH*RQ*sizeof(float));
  cudaMemsetAsync(p_dena, 0, BATCH*RQ*sizeof(float));

  k_qlin2<<<dim3(8,6,3), 256>>>(xmm, fq_w, qv_w, qa_w);
  k_tr<<<dim3(24,24,2), 256>>>(kvv_w, kva_w);
  k_qt2<<<dim3(12,6,2), 256>>>();
  k_scores3<<<dim3(64,11), 96>>>(xv, xa);
  k_ctx3<<<dim3(64,6,2), 96>>>(xv, xa);
  k_ov2<<<dim3(12,4,2), 256>>>(kvv_w, kva_w);
  k_lin_proj<<<dim3(4,6,2), 256>>>(projv_w, projv_b, proja_w, proja_b, out);
  k_lin_kv<<<dim3(4,6,4), 256>>>(fk_w, fv_w, out);
  k_fused<<<BATCH, 128>>>(out, wattn);
  k_lin_fproj<<<dim3(8,6), 256>>>(fproj_w, fproj_b, out);
}

// round 10
// speedup vs baseline: 3.7526x; 1.1206x over previous
#include <cuda_runtime.h>
#include <math.h>
#include <stdint.h>

#define DIM 768
#define NH 12
#define RQ 48
#define ASCALE 0.125f
#define BATCH 64
typedef unsigned long long ull;

__device__ float g_qlin [BATCH*16*DIM];
__device__ float g_kTv  [DIM*DIM];
__device__ float g_kTa  [DIM*DIM];
__device__ float g_qt_v [BATCH*RQ*DIM];   // qtT: [b][k=768][r=48]
__device__ float g_qt_a [BATCH*RQ*DIM];
__device__ float g_expS_v[BATCH*RQ*784];  // expST: [b][m][r=48]
__device__ float g_expS_a[BATCH*RQ*512];
__device__ float g_den_v[BATCH*RQ];
__device__ float g_den_a[BATCH*RQ];
__device__ float g_C_v  [BATCH*RQ*DIM];
__device__ float g_C_a  [BATCH*RQ*DIM];
__device__ float g_o_v  [BATCH*4*DIM];
__device__ float g_o_a  [BATCH*4*DIM];
__device__ float g_kfv  [BATCH*4*DIM];
__device__ float g_kfa  [BATCH*4*DIM];
__device__ float g_vfv  [BATCH*4*DIM];
__device__ float g_vfa  [BATCH*4*DIM];
__device__ float g_of   [BATCH*8*DIM];
__device__ float g_attn [BATCH*NH*8*16];

// ---------------- packed f32x2 helpers (sm_103a FFMA2) ----------------------
__device__ __forceinline__ ull pk2(float x) {
  ull r; unsigned u = __float_as_uint(x);
  asm("mov.b64 %0, {%1, %1};" : "=l"(r) : "r"(u)); return r;
}
__device__ __forceinline__ void fma2(ull &d, ull a, ull b) {
  asm("fma.rn.f32x2 %0, %1, %2, %0;" : "+l"(d) : "l"(a), "l"(b));
}
__device__ __forceinline__ float2 up2(ull v) {
  unsigned lo, hi;
  asm("mov.b64 {%0, %1}, %2;" : "=r"(lo), "=r"(hi) : "l"(v));
  return make_float2(__uint_as_float(lo), __uint_as_float(hi));
}

// ---------------- cp.async helpers ------------------------------------------
__device__ __forceinline__ unsigned su32(const void* p) {
  return (unsigned)__cvta_generic_to_shared(p);
}
__device__ __forceinline__ void cpa(unsigned d, const void* s, int valid) {
  int sz = valid ? 16 : 0;
  asm volatile("cp.async.cg.shared.global [%0], [%1], 16, %2;" :: "r"(d), "l"(s), "r"(sz));
}
#define CP_COMMIT asm volatile("cp.async.commit_group;" ::: "memory")
#define CP_WAIT1  asm volatile("cp.async.wait_group 1;" ::: "memory")
#define CP_WAIT0  asm volatile("cp.async.wait_group 0;" ::: "memory")

// ---------------- generic 64x128 linear tile (K=768), reg-prefetched --------
__device__ __forceinline__ void lin_tile(const float* __restrict__ A, int a_rpb, size_t a_bs,
    const float* __restrict__ W, const float* __restrict__ bias,
    float* __restrict__ D, int d_rpb, size_t d_bs, int r0, int c0) {
  __shared__ float a_s[32][68];
  __shared__ float b_s[32][132];
  int tid = threadIdx.x;
  int tr = tid % 16, tc = tid / 16;
  ull acc[4][4];
#pragma unroll
  for (int i = 0; i < 4; i++)
#pragma unroll
    for (int p = 0; p < 4; p++) acc[i][p] = 0ull;
  float4 pa[2], pw[4];
  int ar[2]; const float* aptr[2];
#pragma unroll
  for (int i = 0; i < 2; i++) {
    int idx = tid + i*256;
    ar[i] = idx & 7;
    int gr = r0 + (idx >> 3);
    aptr[i] = A + (size_t)(gr/a_rpb)*a_bs + (size_t)(gr%a_rpb)*DIM;
  }
#pragma unroll
  for (int i = 0; i < 2; i++) pa[i] = *(const float4*)(aptr[i] + ar[i]*4);
#pragma unroll
  for (int i = 0; i < 4; i++) {
    int idx = tid + i*256;
    pw[i] = *(const float4*)(W + (size_t)(idx>>5)*DIM + c0 + (idx&31)*4);
  }
  for (int t = 0; t < 24; t++) {
#pragma unroll
    for (int i = 0; i < 2; i++) {
      int idx = tid + i*256;
      int r = idx >> 3, kq = idx & 7;
      a_s[kq*4+0][r]=pa[i].x; a_s[kq*4+1][r]=pa[i].y;
      a_s[kq*4+2][r]=pa[i].z; a_s[kq*4+3][r]=pa[i].w;
    }
#pragma unroll
    for (int i = 0; i < 4; i++) {
      int idx = tid + i*256;
      *(float4*)&b_s[idx>>5][(idx&31)*4] = pw[i];
    }
    __syncthreads();
    if (t < 23) {
      int k0 = (t+1)*32;
#pragma unroll
      for (int i = 0; i < 2; i++) pa[i] = *(const float4*)(aptr[i] + k0 + ar[i]*4);
#pragma unroll
      for (int i = 0; i < 4; i++) {
        int idx = tid + i*256;
        pw[i] = *(const float4*)(W + (size_t)(k0 + (idx>>5))*DIM + c0 + (idx&31)*4);
      }
    }
#pragma unroll
    for (int kk = 0; kk < 32; kk++) {
      float4 a4 = *(const float4*)&a_s[kk][tr*4];
      const ull* q0 = (const ull*)&b_s[kk][tc*4];
      const ull* q1 = (const ull*)&b_s[kk][64+tc*4];
      ull bp0=q0[0], bp1=q0[1], bp2=q1[0], bp3=q1[1];
      float av[4] = {a4.x, a4.y, a4.z, a4.w};
#pragma unroll
      for (int i = 0; i < 4; i++) {
        ull ai = pk2(av[i]);
        fma2(acc[i][0],ai,bp0); fma2(acc[i][1],ai,bp1);
        fma2(acc[i][2],ai,bp2); fma2(acc[i][3],ai,bp3);
      }
    }
    __syncthreads();
  }
#pragma unroll
  for (int i = 0; i < 4; i++) {
    int gr = r0 + tr*4 + i;
    float* dp = D + (size_t)(gr/d_rpb)*d_bs + (size_t)(gr%d_rpb)*DIM;
#pragma unroll
    for (int p = 0; p < 4; p++) {
      float2 v = up2(acc[i][p]);
      int c = c0 + (p>>1)*64 + tc*4 + (p&1)*2;
      float bb0 = bias ? bias[c]   : 0.f;
      float bb1 = bias ? bias[c+1] : 0.f;
      dp[c] = v.x + bb0; dp[c+1] = v.y + bb1;
    }
  }
}

// qlin rows 0-7: xmm@fq, 8-11: xmm@qv, 12-15: xmm@qa
__global__ __launch_bounds__(256) void k_qlin2(const float* __restrict__ xmm,
    const float* __restrict__ fq, const float* __restrict__ qv,
    const float* __restrict__ qa) {
  int z = blockIdx.z;
  if (z > 0 && blockIdx.x >= 4) return;
  const float* W = (z==0) ? fq : (z==1 ? qv : qa);
  int off = (z==0) ? 0 : (z==1 ? 8 : 12);
  int rpb = (z==0) ? 8 : 4;
  lin_tile(xmm + (size_t)off*DIM, rpb, (size_t)16*DIM, W, nullptr,
           g_qlin + (size_t)off*DIM, rpb, (size_t)16*DIM,
           blockIdx.x*64, blockIdx.y*128);
}

// transpose K-halves of kvv_w / kva_w
__global__ __launch_bounds__(256) void k_tr(const float* __restrict__ kvv,
                                            const float* __restrict__ kva) {
  __shared__ float t[32][33];
  const float* src = blockIdx.z ? kva : kvv;
  float* dst = blockIdx.z ? g_kTa : g_kTv;
  int x0 = blockIdx.x*32, y0 = blockIdx.y*32;
  int tx = threadIdx.x & 31, ty = threadIdx.x >> 5;
  for (int i = 0; i < 32; i += 8)
    t[ty+i][tx] = src[(size_t)(y0+ty+i)*2*DIM + x0+tx];
  __syncthreads();
  for (int i = 0; i < 32; i += 8)
    dst[(size_t)(x0+ty+i)*DIM + y0+tx] = t[tx][ty+i];
}

// qtT[b][d][r] = ASCALE * sum_e qlin[b,off+n,h*64+e] * kT[h*64+e][d]
__global__ __launch_bounds__(256) void k_qt3() {
  int h = blockIdx.x, d0 = blockIdx.y*128, which = blockIdx.z, tid = threadIdx.x;
  const float* kT = which ? g_kTa : g_kTv;
  float* qt = which ? g_qt_a : g_qt_v;
  int off = which ? 12 : 8;
  __shared__ float kts[64][129];
  __shared__ float qsh[4][64];
#pragma unroll
  for (int i = 0; i < 8; i++) {
    int idx = tid + i*256;
    int e = idx >> 5, cq = idx & 31;
    float4 v = *(const float4*)(kT + (size_t)(h*64+e)*DIM + d0 + cq*4);
    kts[e][cq*4]=v.x; kts[e][cq*4+1]=v.y; kts[e][cq*4+2]=v.z; kts[e][cq*4+3]=v.w;
  }
  int col = tid & 127, rp = tid >> 7;
  for (int b = 0; b < BATCH; b++) {
    __syncthreads();
    { int n = (tid >> 6) & 3, e = tid & 63;
      qsh[n][e] = g_qlin[((size_t)b*16 + off + n)*DIM + h*64 + e]; }
    __syncthreads();
    float a0 = 0.f, a1 = 0.f;
#pragma unroll
    for (int e = 0; e < 64; e++) {
      float w = kts[e][col];
      a0 += qsh[rp*2][e]*w; a1 += qsh[rp*2+1][e]*w;
    }
    *(float2*)&qt[((size_t)b*DIM + d0 + col)*RQ + h*4 + rp*2] =
        make_float2(a0*ASCALE, a1*ASCALE);
  }
}

// expST[m][r] = exp(X @ qtT) + fused row-sum; cp.async double-buffered
__global__ __launch_bounds__(96) void k_scores4(const float* __restrict__ xv,
                                                const float* __restrict__ xa) {
  __shared__ float xs[2][112][36];   // [m][k], pitch 36
  __shared__ float qs[2][32][48];    // [k][r]
  int b = blockIdx.x, y = blockIdx.y, tid = threadIdx.x;
  int which = (y >= 7);
  int m0 = (which ? (y-7) : y) * 112;
  int N2 = which ? 512 : 784;
  const float* X = (which ? xa : xv) + (size_t)b*N2*DIM;
  const float* Q = (which ? g_qt_a : g_qt_v) + (size_t)b*DIM*RQ;
  float* expS = (which ? g_expS_a : g_expS_v) + (size_t)b*N2*RQ;
  float* den  = (which ? g_den_a : g_den_v) + b*RQ;
  int tm = tid & 15, tc = tid >> 4;   // tm: m-lane, tc: r-group (0..5)

  ull acc[7][4];
#pragma unroll
  for (int i = 0; i < 7; i++)
#pragma unroll
    for (int p = 0; p < 4; p++) acc[i][p] = 0ull;

#define LOAD_TILE_S(T, BUF) do {                                            \
    int k0 = (T)*32;                                                        \
_Pragma("unroll")                                                           \
    for (int i = 0; i < 14; i++) {                                          \
      int idx = tid + i*96;                                                 \
      if (idx < 896) {                                                      \
        int m = idx >> 3, c = idx & 7;                                      \
        int ok = (m0+m) < N2;                                               \
        const float* s = X + (size_t)(ok ? (m0+m) : 0)*DIM + k0 + c*4;      \
        cpa(su32(&xs[BUF][m][c*4]), s, ok);                                 \
      } else if (idx < 1280) {                                              \
        int j = idx - 896;                                                  \
        int kr = j / 12, c = j % 12;                                        \
        cpa(su32(&qs[BUF][kr][c*4]), Q + (size_t)(k0+kr)*RQ + c*4, 1);      \
      }                                                                     \
    }                                                                       \
  } while (0)

  LOAD_TILE_S(0, 0); CP_COMMIT;
  for (int t = 0; t < 24; t++) {
    if (t < 23) { LOAD_TILE_S(t+1, (t+1)&1); CP_COMMIT; CP_WAIT1; }
    else        { CP_WAIT0; }
    __syncthreads();
    int buf = t & 1;
#pragma unroll 8
    for (int kk = 0; kk < 32; kk++) {
      const ull* qp = (const ull*)&qs[buf][kk][tc*8];
      ull b0 = qp[0], b1 = qp[1], b2 = qp[2], b3 = qp[3];
#pragma unroll
      for (int i = 0; i < 7; i++) {
        ull ai = pk2(xs[buf][tm + 16*i][kk]);
        fma2(acc[i][0], ai, b0); fma2(acc[i][1], ai, b1);
        fma2(acc[i][2], ai, b2); fma2(acc[i][3], ai, b3);
      }
    }
    __syncthreads();
  }
#undef LOAD_TILE_S
  // epilogue: exp + store + fused denom partials
  float rs[8] = {0.f,0.f,0.f,0.f,0.f,0.f,0.f,0.f};
#pragma unroll
  for (int i = 0; i < 7; i++) {
    int m = m0 + tm + 16*i;
    if (m < N2) {
      float* row = expS + (size_t)m*RQ + tc*8;
#pragma unroll
      for (int p = 0; p < 4; p++) {
        float2 v = up2(acc[i][p]);
        float e0 = __expf(v.x), e1 = __expf(v.y);
        *(float2*)&row[2*p] = make_float2(e0, e1);
        rs[2*p] += e0; rs[2*p+1] += e1;
      }
    }
  }
  float* red = &qs[0][0][0];   // reuse (buf0 not read after t=22 barrier)
#pragma unroll
  for (int p = 0; p < 8; p++) red[(tc*8+p)*16 + tm] = rs[p];
  __syncthreads();
  if (tid < RQ) {
    float s = 0.f;
#pragma unroll
    for (int j = 0; j < 16; j++) s += red[tid*16 + j];
    atomicAdd(&den[tid], s);
  }
}

// C[r][d] = (expST^T @ X)/den; cp.async double-buffered
__global__ __launch_bounds__(96) void k_ctx4(const float* __restrict__ xv,
                                             const float* __restrict__ xa) {
  __shared__ float es[2][32][48];    // [m][r]
  __shared__ float bs[2][32][132];   // [m][d], pitch 132
  int b = blockIdx.x, d0 = blockIdx.y*128, which = blockIdx.z, tid = threadIdx.x;
  int N2 = which ? 512 : 784;
  const float* E = (which ? g_expS_a : g_expS_v) + (size_t)b*N2*RQ;
  const float* X = (which ? xa : xv) + (size_t)b*N2*DIM;
  const float* den = (which ? g_den_a : g_den_v) + b*RQ;
  float* C = (which ? g_C_a : g_C_v) + (size_t)b*RQ*DIM;
  int tc = tid & 15, tr = tid >> 4;   // tr: r-group (0..5), tc: d-quad lane

  ull acc[8][4];
#pragma unroll
  for (int i = 0; i < 8; i++)
#pragma unroll
    for (int p = 0; p < 4; p++) acc[i][p] = 0ull;
  int nt = (N2 + 31) / 32;

#define LOAD_TILE_C(T, BUF) do {                                            \
    int k0 = (T)*32;                                                        \
_Pragma("unroll")                                                           \
    for (int i = 0; i < 15; i++) {                                          \
      int idx = tid + i*96;                                                 \
      if (idx < 1024) {                                                     \
        int mm = idx >> 5, c = idx & 31;                                    \
        int ok = (k0+mm) < N2;                                              \
        const float* s = X + (size_t)(ok ? (k0+mm) : 0)*DIM + d0 + c*4;     \
        cpa(su32(&bs[BUF][mm][c*4]), s, ok);                                \
      } else if (idx < 1408) {                                              \
        int j = idx - 1024;                                                 \
        int mm = j / 12, c = j % 12;                                        \
        int ok = (k0+mm) < N2;                                              \
        const float* s = E + (size_t)(ok ? (k0+mm) : 0)*RQ + c*4;           \
        cpa(su32(&es[BUF][mm][c*4]), s, ok);                                \
      }                                                                     \
    }                                                                       \
  } while (0)

  LOAD_TILE_C(0, 0); CP_COMMIT;
  for (int t = 0; t < nt; t++) {
    if (t+1 < nt) { LOAD_TILE_C(t+1, (t+1)&1); CP_COMMIT; CP_WAIT1; }
    else          { CP_WAIT0; }
    __syncthreads();
    int buf = t & 1;
#pragma unroll 8
    for (int mm = 0; mm < 32; mm++) {
      const ull* p0 = (const ull*)&bs[buf][mm][tc*4];
      const ull* p1 = (const ull*)&bs[buf][mm][64 + tc*4];
      ull b0 = p0[0], b1 = p0[1], b2 = p1[0], b3 = p1[1];
      float4 a0 = *(const float4*)&es[buf][mm][tr*8];
      float4 a1 = *(const float4*)&es[buf][mm][tr*8+4];
      float av[8] = {a0.x,a0.y,a0.z,a0.w,a1.x,a1.y,a1.z,a1.w};
#pragma unroll
      for (int i = 0; i < 8; i++) {
        ull ai = pk2(av[i]);
        fma2(acc[i][0], ai, b0); fma2(acc[i][1], ai, b1);
        fma2(acc[i][2], ai, b2); fma2(acc[i][3], ai, b3);
      }
    }
    __syncthreads();
  }
#undef LOAD_TILE_C
#pragma unroll
  for (int i = 0; i < 8; i++) {
    int r = tr*8 + i;
    float inv = 1.f / den[r];
    float* crow = C + (size_t)r*DIM + d0;
#pragma unroll
    for (int p = 0; p < 4; p++) {
      float2 v = up2(acc[i][p]);
      int c = (p < 2) ? (tc*4 + 2*p) : (64 + tc*4 + 2*(p-2));
      *(float2*)&crow[c] = make_float2(v.x*inv, v.y*inv);
    }
  }
}

// o = C @ Wv-half (per-head)
__global__ __launch_bounds__(256) void k_ov2(const float* __restrict__ kvv,
                                             const float* __restrict__ kva) {
  int h = blockIdx.x, b0 = blockIdx.y*16, which = blockIdx.z, tid = threadIdx.x;
  const float* C = which ? g_C_a : g_C_v;
  const float* kvw = which ? kva : kvv;
  float* o = which ? g_o_a : g_o_v;
  __shared__ float a_s[32][68];
  __shared__ float b_s[32][68];
  int tr = tid % 16, tc = tid / 16;
  ull acc[4][2];
#pragma unroll
  for (int i = 0; i < 4; i++) { acc[i][0]=0ull; acc[i][1]=0ull; }
  for (int k0 = 0; k0 < DIM; k0 += 32) {
    __syncthreads();
#pragma unroll
    for (int i = 0; i < 2; i++) {
      int idx = tid + i*256;
      int r = idx >> 3, kq = idx & 7;
      const float* ap = C + ((size_t)(b0 + (r>>2))*RQ + h*4 + (r&3))*DIM;
      float4 v = *(const float4*)(ap + k0 + kq*4);
      a_s[kq*4+0][r]=v.x; a_s[kq*4+1][r]=v.y; a_s[kq*4+2][r]=v.z; a_s[kq*4+3][r]=v.w;
    }
#pragma unroll
    for (int i = 0; i < 2; i++) {
      int idx = tid + i*256;
      int k = idx >> 4, cq = idx & 15;
      float4 v = *(const float4*)(kvw + (size_t)(k0+k)*2*DIM + DIM + h*64 + cq*4);
      *(float4*)&b_s[k][cq*4] = v;
    }
    __syncthreads();
#pragma unroll
    for (int kk = 0; kk < 32; kk++) {
      float4 a4 = *(const float4*)&a_s[kk][tr*4];
      const ull* q0 = (const ull*)&b_s[kk][tc*4];
      ull bp0 = q0[0], bp1 = q0[1];
      float av[4] = {a4.x, a4.y, a4.z, a4.w};
#pragma unroll
      for (int i = 0; i < 4; i++) {
        ull ai = pk2(av[i]);
        fma2(acc[i][0],ai,bp0); fma2(acc[i][1],ai,bp1);
      }
    }
  }
#pragma unroll
  for (int i = 0; i < 4; i++) {
    int r = tr*4 + i;
    float* dp = o + ((size_t)(b0 + (r>>2))*4 + (r&3))*DIM + h*64;
#pragma unroll
    for (int p = 0; p < 2; p++) {
      float2 v = up2(acc[i][p]);
      int c = tc*4 + p*2;
      dp[c] = v.x; dp[c+1] = v.y;
    }
  }
}

__global__ __launch_bounds__(256) void k_lin_proj(const float* __restrict__ pv_w,
    const float* __restrict__ pv_b, const float* __restrict__ pa_w,
    const float* __restrict__ pa_b, float* __restrict__ out) {
  int z = blockIdx.z;
  lin_tile(z ? g_o_a : g_o_v, 4, (size_t)4*DIM, z ? pa_w : pv_w, z ? pa_b : pv_b,
           out + (size_t)(8 + 4*z)*DIM, 4, (size_t)16*DIM,
           blockIdx.x*64, blockIdx.y*128);
}

__global__ __launch_bounds__(256) void k_lin_kv(const float* __restrict__ fk,
    const float* __restrict__ fv, const float* __restrict__ out) {
  int z = blockIdx.z, half = z & 1;
  const float* W = (z < 2 ? fk : fv) + (size_t)half*DIM*DIM;
  float* D = (z==0) ? g_kfv : (z==1) ? g_kfa : (z==2) ? g_vfv : g_vfa;
  lin_tile(out + (size_t)(8 + 4*half)*DIM, 4, (size_t)16*DIM, W, nullptr,
           D, 4, (size_t)4*DIM, blockIdx.x*64, blockIdx.y*128);
}

__global__ __launch_bounds__(256) void k_lin_fproj(const float* __restrict__ W,
    const float* __restrict__ bias, float* __restrict__ out) {
  lin_tile(g_of, 8, (size_t)8*DIM, W, bias, out, 8, (size_t)16*DIM,
           blockIdx.x*64, blockIdx.y*128);
}

// final 8x16 attention
__global__ __launch_bounds__(128) void k_fused(float* __restrict__ out, int wattn) {
  int b = blockIdx.x, tid = threadIdx.x;
  float* attn = wattn ? (out + (size_t)BATCH*16*DIM) : g_attn;
  __shared__ float qh[8][64], kh[16][64], vh[16][64], ps[8][16];
  int n_s = tid >> 4, t_s = tid & 15;
  for (int h = 0; h < NH; h++) {
    __syncthreads();
    for (int i = tid; i < 512; i += 128) {
      int n = i >> 6, e = i & 63;
      qh[n][e] = g_qlin[((size_t)b*16 + n)*DIM + h*64 + e];
    }
    for (int i = tid; i < 1024; i += 128) {
      int t = i >> 6, e = i & 63;
      kh[t][e] = g_kfv[((size_t)b*4 + (t>>2))*DIM + h*64 + e]
               + g_kfa[((size_t)b*4 + (t&3))*DIM + h*64 + e];
      vh[t][e] = g_vfv[((size_t)b*4 + (t>>2))*DIM + h*64 + e]
               + g_vfa[((size_t)b*4 + (t&3))*DIM + h*64 + e];
    }
    __syncthreads();
    float sc = 0.f;
#pragma unroll 8
    for (int e = 0; e < 64; e++) sc += qh[n_s][e]*kh[t_s][e];
    sc *= ASCALE;
    float mx = sc;
#pragma unroll
    for (int o = 8; o; o >>= 1) mx = fmaxf(mx, __shfl_xor_sync(0xffffffffu, mx, o));
    float ex = expf(sc - mx), sm = ex;
#pragma unroll
    for (int o = 8; o; o >>= 1) sm += __shfl_xor_sync(0xffffffffu, sm, o);
    float p = ex/sm;
    attn[(((size_t)b*NH + h)*8 + n_s)*16 + t_s] = p;
    ps[n_s][t_s] = p;
    __syncthreads();
    for (int i = tid; i < 512; i += 128) {
      int n = i >> 6, e = i & 63;
      float acc = 0.f;
#pragma unroll
      for (int t = 0; t < 16; t++) acc += ps[n][t]*vh[t][e];
      g_of[((size_t)b*8 + n)*DIM + h*64 + e] = acc;
    }
  }
}

extern "C" void kernel_launch(void* const* d_in, const int* in_sizes, int n_in,
                              void* d_out, int out_size) {
  const float* xmm    = (const float*)d_in[0];
  const float* xv     = (const float*)d_in[1];
  const float* xa     = (const float*)d_in[2];
  const float* qv_w   = (const float*)d_in[3];
  const float* kvv_w  = (const float*)d_in[4];
  const float* projv_w= (const float*)d_in[5];
  const float* projv_b= (const float*)d_in[6];
  const float* qa_w   = (const float*)d_in[7];
  const float* kva_w  = (const float*)d_in[8];
  const float* proja_w= (const float*)d_in[9];
  const float* proja_b= (const float*)d_in[10];
  const float* fq_w   = (const float*)d_in[11];
  const float* fk_w   = (const float*)d_in[12];
  const float* fv_w   = (const float*)d_in[13];
  const float* fproj_w= (const float*)d_in[14];
  const float* fproj_b= (const float*)d_in[15];
  float* out = (float*)d_out;
  int wattn = (out_size >= BATCH*16*DIM + BATCH*NH*8*16) ? 1 : 0;

  void *p_denv, *p_dena;
  cudaGetSymbolAddress(&p_denv, g_den_v);
  cudaGetSymbolAddress(&p_dena, g_den_a);
  cudaMemsetAsync(p_denv, 0, BATCH*RQ*sizeof(float));
  cudaMemsetAsync(p_dena, 0, BATCH*RQ*sizeof(float));

  k_qlin2<<<dim3(8,6,3), 256>>>(xmm, fq_w, qv_w, qa_w);
  k_tr<<<dim3(24,24,2), 256>>>(kvv_w, kva_w);
  k_qt3<<<dim3(12,6,2), 256>>>();
  k_scores4<<<dim3(64,12), 96>>>(xv, xa);
  k_ctx4<<<dim3(64,6,2), 96>>>(xv, xa);
  k_ov2<<<dim3(12,4,2), 256>>>(kvv_w, kva_w);
  k_lin_proj<<<dim3(4,6,2), 256>>>(projv_w, projv_b, proja_w, proja_b, out);
  k_lin_kv<<<dim3(4,6,4), 256>>>(fk_w, fv_w, out);
  k_fused<<<BATCH, 128>>>(out, wattn);
  k_lin_fproj<<<dim3(8,6), 256>>>(fproj_w, fproj_b, out);
}

// round 12
// speedup vs baseline: 4.3410x; 1.1568x over previous
#include <cuda_runtime.h>
#include <math.h>
#include <stdint.h>

#define DIM 768
#define NH 12
#define RQ 48
#define ASCALE 0.125f
#define BATCH 64
typedef unsigned long long ull;

__device__ float g_qlin [BATCH*16*DIM];
__device__ float g_kTv  [DIM*DIM];
__device__ float g_kTa  [DIM*DIM];
__device__ float g_qt_v [BATCH*RQ*DIM];   // qtT: [b][k=768][r=48]
__device__ float g_qt_a [BATCH*RQ*DIM];
__device__ float g_expS_v[BATCH*RQ*784];  // expST: [b][m][r=48]
__device__ float g_expS_a[BATCH*RQ*512];
__device__ float g_den_v[BATCH*RQ];
__device__ float g_den_a[BATCH*RQ];
__device__ float g_C_v  [BATCH*RQ*DIM];
__device__ float g_C_a  [BATCH*RQ*DIM];
__device__ float g_o_v  [BATCH*4*DIM];
__device__ float g_o_a  [BATCH*4*DIM];
__device__ float g_kfv  [BATCH*4*DIM];
__device__ float g_kfa  [BATCH*4*DIM];
__device__ float g_vfv  [BATCH*4*DIM];
__device__ float g_vfa  [BATCH*4*DIM];
__device__ float g_of   [BATCH*8*DIM];
__device__ float g_attn [BATCH*NH*8*16];

// ---------------- packed f32x2 helpers (sm_103a FFMA2) ----------------------
__device__ __forceinline__ ull pk2(float x) {
  ull r; unsigned u = __float_as_uint(x);
  asm("mov.b64 %0, {%1, %1};" : "=l"(r) : "r"(u)); return r;
}
__device__ __forceinline__ void fma2(ull &d, ull a, ull b) {
  asm("fma.rn.f32x2 %0, %1, %2, %0;" : "+l"(d) : "l"(a), "l"(b));
}
__device__ __forceinline__ float2 up2(ull v) {
  unsigned lo, hi;
  asm("mov.b64 {%0, %1}, %2;" : "=r"(lo), "=r"(hi) : "l"(v));
  return make_float2(__uint_as_float(lo), __uint_as_float(hi));
}

// ---------------- cp.async helpers ------------------------------------------
__device__ __forceinline__ unsigned su32(const void* p) {
  return (unsigned)__cvta_generic_to_shared(p);
}
__device__ __forceinline__ void cpa(unsigned d, const void* s, int valid) {
  int sz = valid ? 16 : 0;
  asm volatile("cp.async.cg.shared.global [%0], [%1], 16, %2;" :: "r"(d), "l"(s), "r"(sz));
}
#define CP_COMMIT asm volatile("cp.async.commit_group;" ::: "memory")
#define CP_WAIT1  asm volatile("cp.async.wait_group 1;" ::: "memory")
#define CP_WAIT0  asm volatile("cp.async.wait_group 0;" ::: "memory")

// ---------------- small linear tile: 32 rows x 64 cols, 128 threads ---------
__device__ __forceinline__ void lin_tile2(const float* __restrict__ A, int a_rpb, size_t a_bs,
    const float* __restrict__ W, const float* __restrict__ bias,
    float* __restrict__ D, int d_rpb, size_t d_bs, int r0, int c0) {
  __shared__ float a_s[32][36];
  __shared__ float b_s[32][68];
  int tid = threadIdx.x;
  int tr = tid & 7, tc = tid >> 3;
  ull acc[4][2];
#pragma unroll
  for (int i = 0; i < 4; i++) { acc[i][0] = 0ull; acc[i][1] = 0ull; }
  float4 pa[2], pw[4];
  int ak[2]; const float* aptr[2];
#pragma unroll
  for (int i = 0; i < 2; i++) {
    int idx = tid + i*128;
    ak[i] = idx & 7;
    int gr = r0 + (idx >> 3);
    aptr[i] = A + (size_t)(gr/a_rpb)*a_bs + (size_t)(gr%a_rpb)*DIM;
    pa[i] = *(const float4*)(aptr[i] + ak[i]*4);
  }
#pragma unroll
  for (int i = 0; i < 4; i++) {
    int idx = tid + i*128;
    pw[i] = *(const float4*)(W + (size_t)(idx>>4)*DIM + c0 + (idx&15)*4);
  }
  for (int t = 0; t < 24; t++) {
#pragma unroll
    for (int i = 0; i < 2; i++) {
      int idx = tid + i*128;
      int r = idx >> 3, kq = idx & 7;
      a_s[kq*4+0][r]=pa[i].x; a_s[kq*4+1][r]=pa[i].y;
      a_s[kq*4+2][r]=pa[i].z; a_s[kq*4+3][r]=pa[i].w;
    }
#pragma unroll
    for (int i = 0; i < 4; i++) {
      int idx = tid + i*128;
      *(float4*)&b_s[idx>>4][(idx&15)*4] = pw[i];
    }
    __syncthreads();
    if (t < 23) {
      int k0 = (t+1)*32;
#pragma unroll
      for (int i = 0; i < 2; i++) pa[i] = *(const float4*)(aptr[i] + k0 + ak[i]*4);
#pragma unroll
      for (int i = 0; i < 4; i++) {
        int idx = tid + i*128;
        pw[i] = *(const float4*)(W + (size_t)(k0 + (idx>>4))*DIM + c0 + (idx&15)*4);
      }
    }
#pragma unroll
    for (int kk = 0; kk < 32; kk++) {
      float4 a4 = *(const float4*)&a_s[kk][tr*4];
      const ull* q0 = (const ull*)&b_s[kk][tc*4];
      ull b0 = q0[0], b1 = q0[1];
      float av[4] = {a4.x, a4.y, a4.z, a4.w};
#pragma unroll
      for (int i = 0; i < 4; i++) {
        ull ai = pk2(av[i]);
        fma2(acc[i][0],ai,b0); fma2(acc[i][1],ai,b1);
      }
    }
    __syncthreads();
  }
#pragma unroll
  for (int i = 0; i < 4; i++) {
    int gr = r0 + tr*4 + i;
    float* dp = D + (size_t)(gr/d_rpb)*d_bs + (size_t)(gr%d_rpb)*DIM;
#pragma unroll
    for (int p = 0; p < 2; p++) {
      float2 v = up2(acc[i][p]);
      int c = c0 + tc*4 + p*2;
      float bb0 = bias ? bias[c]   : 0.f;
      float bb1 = bias ? bias[c+1] : 0.f;
      *(float2*)&dp[c] = make_float2(v.x + bb0, v.y + bb1);
    }
  }
}

// qlin rows 0-7: xmm@fq, 8-11: xmm@qv, 12-15: xmm@qa
__global__ __launch_bounds__(128) void k_qlin3(const float* __restrict__ xmm,
    const float* __restrict__ fq, const float* __restrict__ qv,
    const float* __restrict__ qa) {
  int z = blockIdx.z;
  if (z > 0 && blockIdx.x >= 8) return;
  const float* W = (z==0) ? fq : (z==1 ? qv : qa);
  int off = (z==0) ? 0 : (z==1 ? 8 : 12);
  int rpb = (z==0) ? 8 : 4;
  lin_tile2(xmm + (size_t)off*DIM, rpb, (size_t)16*DIM, W, nullptr,
            g_qlin + (size_t)off*DIM, rpb, (size_t)16*DIM,
            blockIdx.x*32, blockIdx.y*64);
}

// transpose K-halves of kvv_w / kva_w
__global__ __launch_bounds__(256) void k_tr(const float* __restrict__ kvv,
                                            const float* __restrict__ kva) {
  __shared__ float t[32][33];
  const float* src = blockIdx.z ? kva : kvv;
  float* dst = blockIdx.z ? g_kTa : g_kTv;
  int x0 = blockIdx.x*32, y0 = blockIdx.y*32;
  int tx = threadIdx.x & 31, ty = threadIdx.x >> 5;
  for (int i = 0; i < 32; i += 8)
    t[ty+i][tx] = src[(size_t)(y0+ty+i)*2*DIM + x0+tx];
  __syncthreads();
  for (int i = 0; i < 32; i += 8)
    dst[(size_t)(x0+ty+i)*DIM + y0+tx] = t[tx][ty+i];
}

// qtT[b][d][r] = ASCALE * sum_e qlin[b,off+n,h*64+e] * kT[h*64+e][d]
__global__ __launch_bounds__(256) void k_qt3() {
  int h = blockIdx.x, d0 = blockIdx.y*128, tid = threadIdx.x;
  int which = blockIdx.z >> 2, bg = blockIdx.z & 3;
  const float* kT = which ? g_kTa : g_kTv;
  float* qt = which ? g_qt_a : g_qt_v;
  int off = which ? 12 : 8;
  __shared__ float kts[64][129];
  __shared__ float qsh[4][64];
#pragma unroll
  for (int i = 0; i < 8; i++) {
    int idx = tid + i*256;
    int e = idx >> 5, cq = idx & 31;
    float4 v = *(const float4*)(kT + (size_t)(h*64+e)*DIM + d0 + cq*4);
    kts[e][cq*4]=v.x; kts[e][cq*4+1]=v.y; kts[e][cq*4+2]=v.z; kts[e][cq*4+3]=v.w;
  }
  int col = tid & 127, rp = tid >> 7;
  for (int b = bg*16; b < bg*16 + 16; b++) {
    __syncthreads();
    { int n = (tid >> 6) & 3, e = tid & 63;
      qsh[n][e] = g_qlin[((size_t)b*16 + off + n)*DIM + h*64 + e]; }
    __syncthreads();
    float a0 = 0.f, a1 = 0.f;
#pragma unroll
    for (int e = 0; e < 64; e++) {
      float w = kts[e][col];
      a0 += qsh[rp*2][e]*w; a1 += qsh[rp*2+1][e]*w;
    }
    *(float2*)&qt[((size_t)b*DIM + d0 + col)*RQ + h*4 + rp*2] =
        make_float2(a0*ASCALE, a1*ASCALE);
  }
}

// expST[m][r] = exp(X @ qtT) + fused row-sum; cp.async double-buffered
__global__ __launch_bounds__(96, 5) void k_scores5(const float* __restrict__ xv,
                                                   const float* __restrict__ xa) {
  __shared__ float xs[2][112][36];   // [m][k], pitch 36
  __shared__ float qs[2][32][48];    // [k][r]
  int b = blockIdx.x, y = blockIdx.y, tid = threadIdx.x;
  int which = (y >= 7);
  int m0 = (which ? (y-7) : y) * 112;
  int N2 = which ? 512 : 784;
  const float* X = (which ? xa : xv) + (size_t)b*N2*DIM;
  const float* Q = (which ? g_qt_a : g_qt_v) + (size_t)b*DIM*RQ;
  float* expS = (which ? g_expS_a : g_expS_v) + (size_t)b*N2*RQ;
  float* den  = (which ? g_den_a : g_den_v) + b*RQ;
  int tm = tid & 15, tc = tid >> 4;   // tm: m-lane, tc: r-group (0..5)

  ull acc[7][4];
#pragma unroll
  for (int i = 0; i < 7; i++)
#pragma unroll
    for (int p = 0; p < 4; p++) acc[i][p] = 0ull;

#define LOAD_TILE_S(T, BUF) do {                                            \
    int k0 = (T)*32;                                                        \
_Pragma("unroll")                                                           \
    for (int i = 0; i < 14; i++) {                                          \
      int idx = tid + i*96;                                                 \
      if (idx < 896) {                                                      \
        int m = idx >> 3, c = idx & 7;                                      \
        int ok = (m0+m) < N2;                                               \
        const float* s = X + (size_t)(ok ? (m0+m) : 0)*DIM + k0 + c*4;      \
        cpa(su32(&xs[BUF][m][c*4]), s, ok);                                 \
      } else if (idx < 1280) {                                              \
        int j = idx - 896;                                                  \
        int kr = j / 12, c = j % 12;                                        \
        cpa(su32(&qs[BUF][kr][c*4]), Q + (size_t)(k0+kr)*RQ + c*4, 1);      \
      }                                                                     \
    }                                                                       \
  } while (0)

  LOAD_TILE_S(0, 0); CP_COMMIT;
  for (int t = 0; t < 24; t++) {
    if (t < 23) { LOAD_TILE_S(t+1, (t+1)&1); CP_COMMIT; CP_WAIT1; }
    else        { CP_WAIT0; }
    __syncthreads();
    int buf = t & 1;
#pragma unroll
    for (int k4 = 0; k4 < 8; k4++) {
      float4 xr[7];
#pragma unroll
      for (int i = 0; i < 7; i++)
        xr[i] = *(const float4*)&xs[buf][tm + 16*i][k4*4];
#pragma unroll
      for (int j = 0; j < 4; j++) {
        int kk = k4*4 + j;
        const ull* qp = (const ull*)&qs[buf][kk][tc*8];
        ull b0 = qp[0], b1 = qp[1], b2 = qp[2], b3 = qp[3];
#pragma unroll
        for (int i = 0; i < 7; i++) {
          const float* xp = (const float*)&xr[i];
          ull ai = pk2(xp[j]);
          fma2(acc[i][0], ai, b0); fma2(acc[i][1], ai, b1);
          fma2(acc[i][2], ai, b2); fma2(acc[i][3], ai, b3);
        }
      }
    }
    __syncthreads();
  }
#undef LOAD_TILE_S
  // epilogue: exp + store + fused denom partials
  float rs[8] = {0.f,0.f,0.f,0.f,0.f,0.f,0.f,0.f};
#pragma unroll
  for (int i = 0; i < 7; i++) {
    int m = m0 + tm + 16*i;
    if (m < N2) {
      float* row = expS + (size_t)m*RQ + tc*8;
#pragma unroll
      for (int p = 0; p < 4; p++) {
        float2 v = up2(acc[i][p]);
        float e0 = __expf(v.x), e1 = __expf(v.y);
        *(float2*)&row[2*p] = make_float2(e0, e1);
        rs[2*p] += e0; rs[2*p+1] += e1;
      }
    }
  }
  float* red = &qs[0][0][0];
#pragma unroll
  for (int p = 0; p < 8; p++) red[(tc*8+p)*16 + tm] = rs[p];
  __syncthreads();
  if (tid < RQ) {
    float s = 0.f;
#pragma unroll
    for (int j = 0; j < 16; j++) s += red[tid*16 + j];
    atomicAdd(&den[tid], s);
  }
}

// C[r][d] = (expST^T @ X)/den; cp.async double-buffered
__global__ __launch_bounds__(96) void k_ctx4(const float* __restrict__ xv,
                                             const float* __restrict__ xa) {
  __shared__ float es[2][32][48];    // [m][r]
  __shared__ float bs[2][32][132];   // [m][d], pitch 132
  int b = blockIdx.x, d0 = blockIdx.y*128, which = blockIdx.z, tid = threadIdx.x;
  int N2 = which ? 512 : 784;
  const float* E = (which ? g_expS_a : g_expS_v) + (size_t)b*N2*RQ;
  const float* X = (which ? xa : xv) + (size_t)b*N2*DIM;
  const float* den = (which ? g_den_a : g_den_v) + b*RQ;
  float* C = (which ? g_C_a : g_C_v) + (size_t)b*RQ*DIM;
  int tc = tid & 15, tr = tid >> 4;

  ull acc[8][4];
#pragma unroll
  for (int i = 0; i < 8; i++)
#pragma unroll
    for (int p = 0; p < 4; p++) acc[i][p] = 0ull;
  int nt = (N2 + 31) / 32;

#define LOAD_TILE_C(T, BUF) do {                                            \
    int k0 = (T)*32;                                                        \
_Pragma("unroll")                                                           \
    for (int i = 0; i < 15; i++) {                                          \
      int idx = tid + i*96;                                                 \
      if (idx < 1024) {                                                     \
        int mm = idx >> 5, c = idx & 31;                                    \
        int ok = (k0+mm) < N2;                                              \
        const float* s = X + (size_t)(ok ? (k0+mm) : 0)*DIM + d0 + c*4;     \
        cpa(su32(&bs[BUF][mm][c*4]), s, ok);                                \
      } else if (idx < 1408) {                                              \
        int j = idx - 1024;                                                 \
        int mm = j / 12, c = j % 12;                                        \
        int ok = (k0+mm) < N2;                                              \
        const float* s = E + (size_t)(ok ? (k0+mm) : 0)*RQ + c*4;           \
        cpa(su32(&es[BUF][mm][c*4]), s, ok);                                \
      }                                                                     \
    }                                                                       \
  } while (0)

  LOAD_TILE_C(0, 0); CP_COMMIT;
  for (int t = 0; t < nt; t++) {
    if (t+1 < nt) { LOAD_TILE_C(t+1, (t+1)&1); CP_COMMIT; CP_WAIT1; }
    else          { CP_WAIT0; }
    __syncthreads();
    int buf = t & 1;
#pragma unroll 8
    for (int mm = 0; mm < 32; mm++) {
      const ull* p0 = (const ull*)&bs[buf][mm][tc*4];
      const ull* p1 = (const ull*)&bs[buf][mm][64 + tc*4];
      ull b0 = p0[0], b1 = p0[1], b2 = p1[0], b3 = p1[1];
      float4 a0 = *(const float4*)&es[buf][mm][tr*8];
      float4 a1 = *(const float4*)&es[buf][mm][tr*8+4];
      float av[8] = {a0.x,a0.y,a0.z,a0.w,a1.x,a1.y,a1.z,a1.w};
#pragma unroll
      for (int i = 0; i < 8; i++) {
        ull ai = pk2(av[i]);
        fma2(acc[i][0], ai, b0); fma2(acc[i][1], ai, b1);
        fma2(acc[i][2], ai, b2); fma2(acc[i][3], ai, b3);
      }
    }
    __syncthreads();
  }
#undef LOAD_TILE_C
#pragma unroll
  for (int i = 0; i < 8; i++) {
    int r = tr*8 + i;
    float inv = 1.f / den[r];
    float* crow = C + (size_t)r*DIM + d0;
#pragma unroll
    for (int p = 0; p < 4; p++) {
      float2 v = up2(acc[i][p]);
      int c = (p < 2) ? (tc*4 + 2*p) : (64 + tc*4 + 2*(p-2));
      *(float2*)&crow[c] = make_float2(v.x*inv, v.y*inv);
    }
  }
}

// o = C @ Wv-half (per-head)
__global__ __launch_bounds__(256) void k_ov2(const float* __restrict__ kvv,
                                             const float* __restrict__ kva) {
  int h = blockIdx.x, b0 = blockIdx.y*16, which = blockIdx.z, tid = threadIdx.x;
  const float* C = which ? g_C_a : g_C_v;
  const float* kvw = which ? kva : kvv;
  float* o = which ? g_o_a : g_o_v;
  __shared__ float a_s[32][68];
  __shared__ float b_s[32][68];
  int tr = tid % 16, tc = tid / 16;
  ull acc[4][2];
#pragma unroll
  for (int i = 0; i < 4; i++) { acc[i][0]=0ull; acc[i][1]=0ull; }
  for (int k0 = 0; k0 < DIM; k0 += 32) {
    __syncthreads();
#pragma unroll
    for (int i = 0; i < 2; i++) {
      int idx = tid + i*256;
      int r = idx >> 3, kq = idx & 7;
      const float* ap = C + ((size_t)(b0 + (r>>2))*RQ + h*4 + (r&3))*DIM;
      float4 v = *(const float4*)(ap + k0 + kq*4);
      a_s[kq*4+0][r]=v.x; a_s[kq*4+1][r]=v.y; a_s[kq*4+2][r]=v.z; a_s[kq*4+3][r]=v.w;
    }
#pragma unroll
    for (int i = 0; i < 2; i++) {
      int idx = tid + i*256;
      int k = idx >> 4, cq = idx & 15;
      float4 v = *(const float4*)(kvw + (size_t)(k0+k)*2*DIM + DIM + h*64 + cq*4);
      *(float4*)&b_s[k][cq*4] = v;
    }
    __syncthreads();
#pragma unroll
    for (int kk = 0; kk < 32; kk++) {
      float4 a4 = *(const float4*)&a_s[kk][tr*4];
      const ull* q0 = (const ull*)&b_s[kk][tc*4];
      ull bp0 = q0[0], bp1 = q0[1];
      float av[4] = {a4.x, a4.y, a4.z, a4.w};
#pragma unroll
      for (int i = 0; i < 4; i++) {
        ull ai = pk2(av[i]);
        fma2(acc[i][0],ai,bp0); fma2(acc[i][1],ai,bp1);
      }
    }
  }
#pragma unroll
  for (int i = 0; i < 4; i++) {
    int r = tr*4 + i;
    float* dp = o + ((size_t)(b0 + (r>>2))*4 + (r&3))*DIM + h*64;
#pragma unroll
    for (int p = 0; p < 2; p++) {
      float2 v = up2(acc[i][p]);
      int c = tc*4 + p*2;
      dp[c] = v.x; dp[c+1] = v.y;
    }
  }
}

__global__ __launch_bounds__(128) void k_lin_proj3(const float* __restrict__ pv_w,
    const float* __restrict__ pv_b, const float* __restrict__ pa_w,
    const float* __restrict__ pa_b, float* __restrict__ out) {
  int z = blockIdx.z;
  lin_tile2(z ? g_o_a : g_o_v, 4, (size_t)4*DIM, z ? pa_w : pv_w, z ? pa_b : pv_b,
            out + (size_t)(8 + 4*z)*DIM, 4, (size_t)16*DIM,
            blockIdx.x*32, blockIdx.y*64);
}

__global__ __launch_bounds__(128) void k_lin_kv3(const float* __restrict__ fk,
    const float* __restrict__ fv, const float* __restrict__ out) {
  int z = blockIdx.z, half = z & 1;
  const float* W = (z < 2 ? fk : fv) + (size_t)half*DIM*DIM;
  float* D = (z==0) ? g_kfv : (z==1) ? g_kfa : (z==2) ? g_vfv : g_vfa;
  lin_tile2(out + (size_t)(8 + 4*half)*DIM, 4, (size_t)16*DIM, W, nullptr,
            D, 4, (size_t)4*DIM, blockIdx.x*32, blockIdx.y*64);
}

__global__ __launch_bounds__(128) void k_lin_fproj3(const float* __restrict__ W,
    const float* __restrict__ bias, float* __restrict__ out) {
  lin_tile2(g_of, 8, (size_t)8*DIM, W, bias, out, 8, (size_t)16*DIM,
            blockIdx.x*32, blockIdx.y*64);
}

// final 8x16 attention, one head per block
__global__ __launch_bounds__(128) void k_fused2(float* __restrict__ out, int wattn) {
  int b = blockIdx.x, h = blockIdx.y, tid = threadIdx.x;
  float* attn = wattn ? (out + (size_t)BATCH*16*DIM) : g_attn;
  __shared__ float qh[8][64], kh[16][64], vh[16][64], ps[8][16];
  int n_s = tid >> 4, t_s = tid & 15;
  for (int i = tid; i < 512; i += 128) {
    int n = i >> 6, e = i & 63;
    qh[n][e] = g_qlin[((size_t)b*16 + n)*DIM + h*64 + e];
  }
  for (int i = tid; i < 1024; i += 128) {
    int t = i >> 6, e = i & 63;
    kh[t][e] = g_kfv[((size_t)b*4 + (t>>2))*DIM + h*64 + e]
             + g_kfa[((size_t)b*4 + (t&3))*DIM + h*64 + e];
    vh[t][e] = g_vfv[((size_t)b*4 + (t>>2))*DIM + h*64 + e]
             + g_vfa[((size_t)b*4 + (t&3))*DIM + h*64 + e];
  }
  __syncthreads();
  float sc = 0.f;
#pragma unroll 8
  for (int e = 0; e < 64; e++) sc += qh[n_s][e]*kh[t_s][e];
  sc *= ASCALE;
  float mx = sc;
#pragma unroll
  for (int o = 8; o; o >>= 1) mx = fmaxf(mx, __shfl_xor_sync(0xffffffffu, mx, o));
  float ex = expf(sc - mx), sm = ex;
#pragma unroll
  for (int o = 8; o; o >>= 1) sm += __shfl_xor_sync(0xffffffffu, sm, o);
  float p = ex/sm;
  attn[(((size_t)b*NH + h)*8 + n_s)*16 + t_s] = p;
  ps[n_s][t_s] = p;
  __syncthreads();
  for (int i = tid; i < 512; i += 128) {
    int n = i >> 6, e = i & 63;
    float acc = 0.f;
#pragma unroll
    for (int t = 0; t < 16; t++) acc += ps[n][t]*vh[t][e];
    g_of[((size_t)b*8 + n)*DIM + h*64 + e] = acc;
  }
}

extern "C" void kernel_launch(void* const* d_in, const int* in_sizes, int n_in,
                              void* d_out, int out_size) {
  const float* xmm    = (const float*)d_in[0];
  const float* xv     = (const float*)d_in[1];
  const float* xa     = (const float*)d_in[2];
  const float* qv_w   = (const float*)d_in[3];
  const float* kvv_w  = (const float*)d_in[4];
  const float* projv_w= (const float*)d_in[5];
  const float* projv_b= (const float*)d_in[6];
  const float* qa_w   = (const float*)d_in[7];
  const float* kva_w  = (const float*)d_in[8];
  const float* proja_w= (const float*)d_in[9];
  const float* proja_b= (const float*)d_in[10];
  const float* fq_w   = (const float*)d_in[11];
  const float* fk_w   = (const float*)d_in[12];
  const float* fv_w   = (const float*)d_in[13];
  const float* fproj_w= (const float*)d_in[14];
  const float* fproj_b= (const float*)d_in[15];
  float* out = (float*)d_out;
  int wattn = (out_size >= BATCH*16*DIM + BATCH*NH*8*16) ? 1 : 0;

  void *p_denv, *p_dena;
  cudaGetSymbolAddress(&p_denv, g_den_v);
  cudaGetSymbolAddress(&p_dena, g_den_a);
  cudaMemsetAsync(p_denv, 0, BATCH*RQ*sizeof(float));
  cudaMemsetAsync(p_dena, 0, BATCH*RQ*sizeof(float));

  k_qlin3<<<dim3(16,12,3), 128>>>(xmm, fq_w, qv_w, qa_w);
  k_tr<<<dim3(24,24,2), 256>>>(kvv_w, kva_w);
  k_qt3<<<dim3(12,6,8), 256>>>();
  k_scores5<<<dim3(64,12), 96>>>(xv, xa);
  k_ctx4<<<dim3(64,6,2), 96>>>(xv, xa);
  k_ov2<<<dim3(12,4,2), 256>>>(kvv_w, kva_w);
  k_lin_proj3<<<dim3(8,12,2), 128>>>(projv_w, projv_b, proja_w, proja_b, out);
  k_lin_kv3<<<dim3(8,12,4), 128>>>(fk_w, fv_w, out);
  k_fused2<<<dim3(64,12), 128>>>(out, wattn);
  k_lin_fproj3<<<dim3(16,12), 128>>>(fproj_w, fproj_b, out);
}

// round 13
// speedup vs baseline: 4.4060x; 1.0150x over previous
#include <cuda_runtime.h>
#include <math.h>
#include <stdint.h>

#define DIM 768
#define NH 12
#define RQ 48
#define ASCALE 0.125f
#define BATCH 64
typedef unsigned long long ull;

__device__ float g_qlin [BATCH*16*DIM];
__device__ float g_kTv  [DIM*DIM];
__device__ float g_kTa  [DIM*DIM];
__device__ float g_qt_v [BATCH*RQ*DIM];   // qtT: [b][k=768][r=48]
__device__ float g_qt_a [BATCH*RQ*DIM];
__device__ float g_expS_v[BATCH*RQ*784];  // expST: [b][m][r=48]
__device__ float g_expS_a[BATCH*RQ*512];
__device__ float g_den_v[BATCH*RQ];
__device__ float g_den_a[BATCH*RQ];
__device__ float g_C_v  [BATCH*RQ*DIM];
__device__ float g_C_a  [BATCH*RQ*DIM];
__device__ float g_o_v  [BATCH*4*DIM];
__device__ float g_o_a  [BATCH*4*DIM];
__device__ float g_kfv  [BATCH*4*DIM];
__device__ float g_kfa  [BATCH*4*DIM];
__device__ float g_vfv  [BATCH*4*DIM];
__device__ float g_vfa  [BATCH*4*DIM];
__device__ float g_of   [BATCH*8*DIM];
__device__ float g_attn [BATCH*NH*8*16];

// ---------------- packed f32x2 helpers (sm_103a FFMA2) ----------------------
__device__ __forceinline__ ull pk2(float x) {
  ull r; unsigned u = __float_as_uint(x);
  asm("mov.b64 %0, {%1, %1};" : "=l"(r) : "r"(u)); return r;
}
__device__ __forceinline__ void fma2(ull &d, ull a, ull b) {
  asm("fma.rn.f32x2 %0, %1, %2, %0;" : "+l"(d) : "l"(a), "l"(b));
}
__device__ __forceinline__ float2 up2(ull v) {
  unsigned lo, hi;
  asm("mov.b64 {%0, %1}, %2;" : "=r"(lo), "=r"(hi) : "l"(v));
  return make_float2(__uint_as_float(lo), __uint_as_float(hi));
}

// ---------------- cp.async helpers ------------------------------------------
__device__ __forceinline__ unsigned su32(const void* p) {
  return (unsigned)__cvta_generic_to_shared(p);
}
__device__ __forceinline__ void cpa(unsigned d, const void* s, int valid) {
  int sz = valid ? 16 : 0;
  asm volatile("cp.async.cg.shared.global [%0], [%1], 16, %2;" :: "r"(d), "l"(s), "r"(sz));
}
#define CP_COMMIT asm volatile("cp.async.commit_group;" ::: "memory")
#define CP_WAIT1  asm volatile("cp.async.wait_group 1;" ::: "memory")
#define CP_WAIT0  asm volatile("cp.async.wait_group 0;" ::: "memory")

// ---------------- small linear tile: 32 rows x 64 cols, 128 threads ---------
__device__ __forceinline__ void lin_tile2(const float* __restrict__ A, int a_rpb, size_t a_bs,
    const float* __restrict__ W, const float* __restrict__ bias,
    float* __restrict__ D, int d_rpb, size_t d_bs, int r0, int c0) {
  __shared__ float a_s[32][36];
  __shared__ float b_s[32][68];
  int tid = threadIdx.x;
  int tr = tid & 7, tc = tid >> 3;
  ull acc[4][2];
#pragma unroll
  for (int i = 0; i < 4; i++) { acc[i][0] = 0ull; acc[i][1] = 0ull; }
  float4 pa[2], pw[4];
  int ak[2]; const float* aptr[2];
#pragma unroll
  for (int i = 0; i < 2; i++) {
    int idx = tid + i*128;
    ak[i] = idx & 7;
    int gr = r0 + (idx >> 3);
    aptr[i] = A + (size_t)(gr/a_rpb)*a_bs + (size_t)(gr%a_rpb)*DIM;
    pa[i] = *(const float4*)(aptr[i] + ak[i]*4);
  }
#pragma unroll
  for (int i = 0; i < 4; i++) {
    int idx = tid + i*128;
    pw[i] = *(const float4*)(W + (size_t)(idx>>4)*DIM + c0 + (idx&15)*4);
  }
  for (int t = 0; t < 24; t++) {
#pragma unroll
    for (int i = 0; i < 2; i++) {
      int idx = tid + i*128;
      int r = idx >> 3, kq = idx & 7;
      a_s[kq*4+0][r]=pa[i].x; a_s[kq*4+1][r]=pa[i].y;
      a_s[kq*4+2][r]=pa[i].z; a_s[kq*4+3][r]=pa[i].w;
    }
#pragma unroll
    for (int i = 0; i < 4; i++) {
      int idx = tid + i*128;
      *(float4*)&b_s[idx>>4][(idx&15)*4] = pw[i];
    }
    __syncthreads();
    if (t < 23) {
      int k0 = (t+1)*32;
#pragma unroll
      for (int i = 0; i < 2; i++) pa[i] = *(const float4*)(aptr[i] + k0 + ak[i]*4);
#pragma unroll
      for (int i = 0; i < 4; i++) {
        int idx = tid + i*128;
        pw[i] = *(const float4*)(W + (size_t)(k0 + (idx>>4))*DIM + c0 + (idx&15)*4);
      }
    }
#pragma unroll
    for (int kk = 0; kk < 32; kk++) {
      float4 a4 = *(const float4*)&a_s[kk][tr*4];
      const ull* q0 = (const ull*)&b_s[kk][tc*4];
      ull b0 = q0[0], b1 = q0[1];
      float av[4] = {a4.x, a4.y, a4.z, a4.w};
#pragma unroll
      for (int i = 0; i < 4; i++) {
        ull ai = pk2(av[i]);
        fma2(acc[i][0],ai,b0); fma2(acc[i][1],ai,b1);
      }
    }
    __syncthreads();
  }
#pragma unroll
  for (int i = 0; i < 4; i++) {
    int gr = r0 + tr*4 + i;
    float* dp = D + (size_t)(gr/d_rpb)*d_bs + (size_t)(gr%d_rpb)*DIM;
#pragma unroll
    for (int p = 0; p < 2; p++) {
      float2 v = up2(acc[i][p]);
      int c = c0 + tc*4 + p*2;
      float bb0 = bias ? bias[c]   : 0.f;
      float bb1 = bias ? bias[c+1] : 0.f;
      *(float2*)&dp[c] = make_float2(v.x + bb0, v.y + bb1);
    }
  }
}

// qlin rows 0-7: xmm@fq, 8-11: xmm@qv, 12-15: xmm@qa
__global__ __launch_bounds__(128) void k_qlin3(const float* __restrict__ xmm,
    const float* __restrict__ fq, const float* __restrict__ qv,
    const float* __restrict__ qa) {
  int z = blockIdx.z;
  if (z > 0 && blockIdx.x >= 8) return;
  const float* W = (z==0) ? fq : (z==1 ? qv : qa);
  int off = (z==0) ? 0 : (z==1 ? 8 : 12);
  int rpb = (z==0) ? 8 : 4;
  lin_tile2(xmm + (size_t)off*DIM, rpb, (size_t)16*DIM, W, nullptr,
            g_qlin + (size_t)off*DIM, rpb, (size_t)16*DIM,
            blockIdx.x*32, blockIdx.y*64);
}

// transpose K-halves of kvv_w / kva_w
__global__ __launch_bounds__(256) void k_tr(const float* __restrict__ kvv,
                                            const float* __restrict__ kva) {
  __shared__ float t[32][33];
  const float* src = blockIdx.z ? kva : kvv;
  float* dst = blockIdx.z ? g_kTa : g_kTv;
  int x0 = blockIdx.x*32, y0 = blockIdx.y*32;
  int tx = threadIdx.x & 31, ty = threadIdx.x >> 5;
  for (int i = 0; i < 32; i += 8)
    t[ty+i][tx] = src[(size_t)(y0+ty+i)*2*DIM + x0+tx];
  __syncthreads();
  for (int i = 0; i < 32; i += 8)
    dst[(size_t)(x0+ty+i)*DIM + y0+tx] = t[tx][ty+i];
}

// qtT[b][d][r] = ASCALE * sum_e qlin[b,off+n,h*64+e] * kT[h*64+e][d]
__global__ __launch_bounds__(256) void k_qt3() {
  int h = blockIdx.x, d0 = blockIdx.y*128, tid = threadIdx.x;
  int which = blockIdx.z >> 2, bg = blockIdx.z & 3;
  const float* kT = which ? g_kTa : g_kTv;
  float* qt = which ? g_qt_a : g_qt_v;
  int off = which ? 12 : 8;
  __shared__ float kts[64][129];
  __shared__ float qsh[4][64];
#pragma unroll
  for (int i = 0; i < 8; i++) {
    int idx = tid + i*256;
    int e = idx >> 5, cq = idx & 31;
    float4 v = *(const float4*)(kT + (size_t)(h*64+e)*DIM + d0 + cq*4);
    kts[e][cq*4]=v.x; kts[e][cq*4+1]=v.y; kts[e][cq*4+2]=v.z; kts[e][cq*4+3]=v.w;
  }
  int col = tid & 127, rp = tid >> 7;
  for (int b = bg*16; b < bg*16 + 16; b++) {
    __syncthreads();
    { int n = (tid >> 6) & 3, e = tid & 63;
      qsh[n][e] = g_qlin[((size_t)b*16 + off + n)*DIM + h*64 + e]; }
    __syncthreads();
    float a0 = 0.f, a1 = 0.f;
#pragma unroll
    for (int e = 0; e < 64; e++) {
      float w = kts[e][col];
      a0 += qsh[rp*2][e]*w; a1 += qsh[rp*2+1][e]*w;
    }
    *(float2*)&qt[((size_t)b*DIM + d0 + col)*RQ + h*4 + rp*2] =
        make_float2(a0*ASCALE, a1*ASCALE);
  }
}

// expST[m][r] = exp(X @ qtT) + fused row-sum; 192 thr, m-tile 128
__global__ __launch_bounds__(192, 4) void k_scores6(const float* __restrict__ xv,
                                                    const float* __restrict__ xa) {
  __shared__ float xs[2][128][36];   // [m][k], pitch 36
  __shared__ float qs[2][32][48];    // [k][r]
  int b = blockIdx.x, y = blockIdx.y, tid = threadIdx.x;
  int which = (y >= 7);
  int m0 = (which ? (y-7) : y) * 128;
  int N2 = which ? 512 : 784;
  const float* X = (which ? xa : xv) + (size_t)b*N2*DIM;
  const float* Q = (which ? g_qt_a : g_qt_v) + (size_t)b*DIM*RQ;
  float* expS = (which ? g_expS_a : g_expS_v) + (size_t)b*N2*RQ;
  float* den  = (which ? g_den_a : g_den_v) + b*RQ;
  int tm = tid & 15, tc = tid >> 4;   // tm: m-lane (8 m's), tc: r-group 0..11 (4 r's)

  ull acc[8][2];
#pragma unroll
  for (int i = 0; i < 8; i++) { acc[i][0] = 0ull; acc[i][1] = 0ull; }

#define LOAD_TILE_S(T, BUF) do {                                            \
    int k0 = (T)*32;                                                        \
_Pragma("unroll")                                                           \
    for (int i = 0; i < 8; i++) {                                           \
      int idx = tid + i*192;                                                \
      if (idx < 1024) {                                                     \
        int m = idx >> 3, c = idx & 7;                                      \
        int ok = (m0+m) < N2;                                               \
        const float* s = X + (size_t)(ok ? (m0+m) : 0)*DIM + k0 + c*4;      \
        cpa(su32(&xs[BUF][m][c*4]), s, ok);                                 \
      } else if (idx < 1408) {                                              \
        int j = idx - 1024;                                                 \
        int kr = j / 12, c = j % 12;                                        \
        cpa(su32(&qs[BUF][kr][c*4]), Q + (size_t)(k0+kr)*RQ + c*4, 1);      \
      }                                                                     \
    }                                                                       \
  } while (0)

  LOAD_TILE_S(0, 0); CP_COMMIT;
  for (int t = 0; t < 24; t++) {
    if (t < 23) { LOAD_TILE_S(t+1, (t+1)&1); CP_COMMIT; CP_WAIT1; }
    else        { CP_WAIT0; }
    __syncthreads();
    int buf = t & 1;
#pragma unroll 8
    for (int kk = 0; kk < 32; kk++) {
      const ull* qp = (const ull*)&qs[buf][kk][tc*4];
      ull b0 = qp[0], b1 = qp[1];
#pragma unroll
      for (int i = 0; i < 8; i++) {
        ull ai = pk2(xs[buf][tm + 16*i][kk]);
        fma2(acc[i][0], ai, b0); fma2(acc[i][1], ai, b1);
      }
    }
    __syncthreads();
  }
#undef LOAD_TILE_S
  // epilogue: exp + store + fused denom partials
  float rs[4] = {0.f,0.f,0.f,0.f};
#pragma unroll
  for (int i = 0; i < 8; i++) {
    int m = m0 + tm + 16*i;
    if (m < N2) {
      float* row = expS + (size_t)m*RQ + tc*4;
#pragma unroll
      for (int p = 0; p < 2; p++) {
        float2 v = up2(acc[i][p]);
        float e0 = __expf(v.x), e1 = __expf(v.y);
        *(float2*)&row[2*p] = make_float2(e0, e1);
        rs[2*p] += e0; rs[2*p+1] += e1;
      }
    }
  }
  float* red = &qs[0][0][0];   // 48*16 floats, reuse after final barrier
#pragma unroll
  for (int p = 0; p < 4; p++) red[(tc*4+p)*16 + tm] = rs[p];
  __syncthreads();
  if (tid < RQ) {
    float s = 0.f;
#pragma unroll
    for (int j = 0; j < 16; j++) s += red[tid*16 + j];
    atomicAdd(&den[tid], s);
  }
}

// C[r][d] = (expST^T @ X)/den; 192 thr
__global__ __launch_bounds__(192, 4) void k_ctx5(const float* __restrict__ xv,
                                                 const float* __restrict__ xa) {
  __shared__ float es[2][32][48];    // [m][r]
  __shared__ float bs[2][32][132];   // [m][d], pitch 132
  int b = blockIdx.x, d0 = blockIdx.y*128, which = blockIdx.z, tid = threadIdx.x;
  int N2 = which ? 512 : 784;
  const float* E = (which ? g_expS_a : g_expS_v) + (size_t)b*N2*RQ;
  const float* X = (which ? xa : xv) + (size_t)b*N2*DIM;
  const float* den = (which ? g_den_a : g_den_v) + b*RQ;
  float* C = (which ? g_C_a : g_C_v) + (size_t)b*RQ*DIM;
  int tc = tid & 15, tr = tid >> 4;   // tr: r-group 0..11 (4 r's), tc: d-quad lane

  ull acc[4][4];
#pragma unroll
  for (int i = 0; i < 4; i++)
#pragma unroll
    for (int p = 0; p < 4; p++) acc[i][p] = 0ull;
  int nt = (N2 + 31) / 32;

#define LOAD_TILE_C(T, BUF) do {                                            \
    int k0 = (T)*32;                                                        \
_Pragma("unroll")                                                           \
    for (int i = 0; i < 8; i++) {                                           \
      int idx = tid + i*192;                                                \
      if (idx < 1024) {                                                     \
        int mm = idx >> 5, c = idx & 31;                                    \
        int ok = (k0+mm) < N2;                                              \
        const float* s = X + (size_t)(ok ? (k0+mm) : 0)*DIM + d0 + c*4;     \
        cpa(su32(&bs[BUF][mm][c*4]), s, ok);                                \
      } else if (idx < 1408) {                                              \
        int j = idx - 1024;                                                 \
        int mm = j / 12, c = j % 12;                                        \
        int ok = (k0+mm) < N2;                                              \
        const float* s = E + (size_t)(ok ? (k0+mm) : 0)*RQ + c*4;           \
        cpa(su32(&es[BUF][mm][c*4]), s, ok);                                \
      }                                                                     \
    }                                                                       \
  } while (0)

  LOAD_TILE_C(0, 0); CP_COMMIT;
  for (int t = 0; t < nt; t++) {
    if (t+1 < nt) { LOAD_TILE_C(t+1, (t+1)&1); CP_COMMIT; CP_WAIT1; }
    else          { CP_WAIT0; }
    __syncthreads();
    int buf = t & 1;
#pragma unroll 8
    for (int mm = 0; mm < 32; mm++) {
      const ull* p0 = (const ull*)&bs[buf][mm][tc*4];
      const ull* p1 = (const ull*)&bs[buf][mm][64 + tc*4];
      ull b0 = p0[0], b1 = p0[1], b2 = p1[0], b3 = p1[1];
      float4 a4 = *(const float4*)&es[buf][mm][tr*4];
      float av[4] = {a4.x, a4.y, a4.z, a4.w};
#pragma unroll
      for (int i = 0; i < 4; i++) {
        ull ai = pk2(av[i]);
        fma2(acc[i][0], ai, b0); fma2(acc[i][1], ai, b1);
        fma2(acc[i][2], ai, b2); fma2(acc[i][3], ai, b3);
      }
    }
    __syncthreads();
  }
#undef LOAD_TILE_C
#pragma unroll
  for (int i = 0; i < 4; i++) {
    int r = tr*4 + i;
    float inv = 1.f / den[r];
    float* crow = C + (size_t)r*DIM + d0;
#pragma unroll
    for (int p = 0; p < 4; p++) {
      float2 v = up2(acc[i][p]);
      int c = (p < 2) ? (tc*4 + 2*p) : (64 + tc*4 + 2*(p-2));
      *(float2*)&crow[c] = make_float2(v.x*inv, v.y*inv);
    }
  }
}

// o = C @ Wv-half (per-head)
__global__ __launch_bounds__(256) void k_ov2(const float* __restrict__ kvv,
                                             const float* __restrict__ kva) {
  int h = blockIdx.x, b0 = blockIdx.y*16, which = blockIdx.z, tid = threadIdx.x;
  const float* C = which ? g_C_a : g_C_v;
  const float* kvw = which ? kva : kvv;
  float* o = which ? g_o_a : g_o_v;
  __shared__ float a_s[32][68];
  __shared__ float b_s[32][68];
  int tr = tid % 16, tc = tid / 16;
  ull acc[4][2];
#pragma unroll
  for (int i = 0; i < 4; i++) { acc[i][0]=0ull; acc[i][1]=0ull; }
  for (int k0 = 0; k0 < DIM; k0 += 32) {
    __syncthreads();
#pragma unroll
    for (int i = 0; i < 2; i++) {
      int idx = tid + i*256;
      int r = idx >> 3, kq = idx & 7;
      const float* ap = C + ((size_t)(b0 + (r>>2))*RQ + h*4 + (r&3))*DIM;
      float4 v = *(const float4*)(ap + k0 + kq*4);
      a_s[kq*4+0][r]=v.x; a_s[kq*4+1][r]=v.y; a_s[kq*4+2][r]=v.z; a_s[kq*4+3][r]=v.w;
    }
#pragma unroll
    for (int i = 0; i < 2; i++) {
      int idx = tid + i*256;
      int k = idx >> 4, cq = idx & 15;
      float4 v = *(const float4*)(kvw + (size_t)(k0+k)*2*DIM + DIM + h*64 + cq*4);
      *(float4*)&b_s[k][cq*4] = v;
    }
    __syncthreads();
#pragma unroll
    for (int kk = 0; kk < 32; kk++) {
      float4 a4 = *(const float4*)&a_s[kk][tr*4];
      const ull* q0 = (const ull*)&b_s[kk][tc*4];
      ull bp0 = q0[0], bp1 = q0[1];
      float av[4] = {a4.x, a4.y, a4.z, a4.w};
#pragma unroll
      for (int i = 0; i < 4; i++) {
        ull ai = pk2(av[i]);
        fma2(acc[i][0],ai,bp0); fma2(acc[i][1],ai,bp1);
      }
    }
  }
#pragma unroll
  for (int i = 0; i < 4; i++) {
    int r = tr*4 + i;
    float* dp = o + ((size_t)(b0 + (r>>2))*4 + (r&3))*DIM + h*64;
#pragma unroll
    for (int p = 0; p < 2; p++) {
      float2 v = up2(acc[i][p]);
      int c = tc*4 + p*2;
      dp[c] = v.x; dp[c+1] = v.y;
    }
  }
}

__global__ __launch_bounds__(128) void k_lin_proj3(const float* __restrict__ pv_w,
    const float* __restrict__ pv_b, const float* __restrict__ pa_w,
    const float* __restrict__ pa_b, float* __restrict__ out) {
  int z = blockIdx.z;
  lin_tile2(z ? g_o_a : g_o_v, 4, (size_t)4*DIM, z ? pa_w : pv_w, z ? pa_b : pv_b,
            out + (size_t)(8 + 4*z)*DIM, 4, (size_t)16*DIM,
            blockIdx.x*32, blockIdx.y*64);
}

__global__ __launch_bounds__(128) void k_lin_kv3(const float* __restrict__ fk,
    const float* __restrict__ fv, const float* __restrict__ out) {
  int z = blockIdx.z, half = z & 1;
  const float* W = (z < 2 ? fk : fv) + (size_t)half*DIM*DIM;
  float* D = (z==0) ? g_kfv : (z==1) ? g_kfa : (z==2) ? g_vfv : g_vfa;
  lin_tile2(out + (size_t)(8 + 4*half)*DIM, 4, (size_t)16*DIM, W, nullptr,
            D, 4, (size_t)4*DIM, blockIdx.x*32, blockIdx.y*64);
}

__global__ __launch_bounds__(128) void k_lin_fproj3(const float* __restrict__ W,
    const float* __restrict__ bias, float* __restrict__ out) {
  lin_tile2(g_of, 8, (size_t)8*DIM, W, bias, out, 8, (size_t)16*DIM,
            blockIdx.x*32, blockIdx.y*64);
}

// final 8x16 attention, one head per block
__global__ __launch_bounds__(128) void k_fused2(float* __restrict__ out, int wattn) {
  int b = blockIdx.x, h = blockIdx.y, tid = threadIdx.x;
  float* attn = wattn ? (out + (size_t)BATCH*16*DIM) : g_attn;
  __shared__ float qh[8][64], kh[16][64], vh[16][64], ps[8][16];
  int n_s = tid >> 4, t_s = tid & 15;
  for (int i = tid; i < 512; i += 128) {
    int n = i >> 6, e = i & 63;
    qh[n][e] = g_qlin[((size_t)b*16 + n)*DIM + h*64 + e];
  }
  for (int i = tid; i < 1024; i += 128) {
    int t = i >> 6, e = i & 63;
    kh[t][e] = g_kfv[((size_t)b*4 + (t>>2))*DIM + h*64 + e]
             + g_kfa[((size_t)b*4 + (t&3))*DIM + h*64 + e];
    vh[t][e] = g_vfv[((size_t)b*4 + (t>>2))*DIM + h*64 + e]
             + g_vfa[((size_t)b*4 + (t&3))*DIM + h*64 + e];
  }
  __syncthreads();
  float sc = 0.f;
#pragma unroll 8
  for (int e = 0; e < 64; e++) sc += qh[n_s][e]*kh[t_s][e];
  sc *= ASCALE;
  float mx = sc;
#pragma unroll
  for (int o = 8; o; o >>= 1) mx = fmaxf(mx, __shfl_xor_sync(0xffffffffu, mx, o));
  float ex = expf(sc - mx), sm = ex;
#pragma unroll
  for (int o = 8; o; o >>= 1) sm += __shfl_xor_sync(0xffffffffu, sm, o);
  float p = ex/sm;
  attn[(((size_t)b*NH + h)*8 + n_s)*16 + t_s] = p;
  ps[n_s][t_s] = p;
  __syncthreads();
  for (int i = tid; i < 512; i += 128) {
    int n = i >> 6, e = i & 63;
    float acc = 0.f;
#pragma unroll
    for (int t = 0; t < 16; t++) acc += ps[n][t]*vh[t][e];
    g_of[((size_t)b*8 + n)*DIM + h*64 + e] = acc;
  }
}

extern "C" void kernel_launch(void* const* d_in, const int* in_sizes, int n_in,
                              void* d_out, int out_size) {
  const float* xmm    = (const float*)d_in[0];
  const float* xv     = (const float*)d_in[1];
  const float* xa     = (const float*)d_in[2];
  const float* qv_w   = (const float*)d_in[3];
  const float* kvv_w  = (const float*)d_in[4];
  const float* projv_w= (const float*)d_in[5];
  const float* projv_b= (const float*)d_in[6];
  const float* qa_w   = (const float*)d_in[7];
  const float* kva_w  = (const float*)d_in[8];
  const float* proja_w= (const float*)d_in[9];
  const float* proja_b= (const float*)d_in[10];
  const float* fq_w   = (const float*)d_in[11];
  const float* fk_w   = (const float*)d_in[12];
  const float* fv_w   = (const float*)d_in[13];
  const float* fproj_w= (const float*)d_in[14];
  const float* fproj_b= (const float*)d_in[15];
  float* out = (float*)d_out;
  int wattn = (out_size >= BATCH*16*DIM + BATCH*NH*8*16) ? 1 : 0;

  void *p_denv, *p_dena;
  cudaGetSymbolAddress(&p_denv, g_den_v);
  cudaGetSymbolAddress(&p_dena, g_den_a);
  cudaMemsetAsync(p_denv, 0, BATCH*RQ*sizeof(float));
  cudaMemsetAsync(p_dena, 0, BATCH*RQ*sizeof(float));

  k_qlin3<<<dim3(16,12,3), 128>>>(xmm, fq_w, qv_w, qa_w);
  k_tr<<<dim3(24,24,2), 256>>>(kvv_w, kva_w);
  k_qt3<<<dim3(12,6,8), 256>>>();
  k_scores6<<<dim3(64,11), 192>>>(xv, xa);
  k_ctx5<<<dim3(64,6,2), 192>>>(xv, xa);
  k_ov2<<<dim3(12,4,2), 256>>>(kvv_w, kva_w);
  k_lin_proj3<<<dim3(8,12,2), 128>>>(projv_w, projv_b, proja_w, proja_b, out);
  k_lin_kv3<<<dim3(8,12,4), 128>>>(fk_w, fv_w, out);
  k_fused2<<<dim3(64,12), 128>>>(out, wattn);
  k_lin_fproj3<<<dim3(16,12), 128>>>(fproj_w, fproj_b, out);
}

// round 15
// speedup vs baseline: 4.4367x; 1.0070x over previous
#include <cuda_runtime.h>
#include <math.h>
#include <stdint.h>

#define DIM 768
#define NH 12
#define RQ 48
#define ASCALE 0.125f
#define BATCH 64
typedef unsigned long long ull;

__device__ float g_qlin [BATCH*16*DIM];
__device__ float g_kTv  [DIM*DIM];
__device__ float g_kTa  [DIM*DIM];
__device__ float g_qt_v [BATCH*RQ*DIM];   // qtT: [b][k=768][r=48]
__device__ float g_qt_a [BATCH*RQ*DIM];
__device__ float g_expS_v[BATCH*RQ*784];  // expST: [b][m][r=48]
__device__ float g_expS_a[BATCH*RQ*512];
__device__ float g_den_v[BATCH*RQ];
__device__ float g_den_a[BATCH*RQ];
__device__ float g_C_v  [BATCH*RQ*DIM];
__device__ float g_C_a  [BATCH*RQ*DIM];
__device__ float g_o_v  [BATCH*4*DIM];
__device__ float g_o_a  [BATCH*4*DIM];
__device__ float g_kfv  [BATCH*4*DIM];
__device__ float g_kfa  [BATCH*4*DIM];
__device__ float g_vfv  [BATCH*4*DIM];
__device__ float g_vfa  [BATCH*4*DIM];
__device__ float g_of   [BATCH*8*DIM];
__device__ float g_attn [BATCH*NH*8*16];

// ---------------- packed f32x2 helpers (sm_103a FFMA2) ----------------------
__device__ __forceinline__ ull pk2(float x) {
  ull r; unsigned u = __float_as_uint(x);
  asm("mov.b64 %0, {%1, %1};" : "=l"(r) : "r"(u)); return r;
}
__device__ __forceinline__ void fma2(ull &d, ull a, ull b) {
  asm("fma.rn.f32x2 %0, %1, %2, %0;" : "+l"(d) : "l"(a), "l"(b));
}
__device__ __forceinline__ float2 up2(ull v) {
  unsigned lo, hi;
  asm("mov.b64 {%0, %1}, %2;" : "=r"(lo), "=r"(hi) : "l"(v));
  return make_float2(__uint_as_float(lo), __uint_as_float(hi));
}

// ---------------- cp.async helpers ------------------------------------------
__device__ __forceinline__ unsigned su32(const void* p) {
  return (unsigned)__cvta_generic_to_shared(p);
}
__device__ __forceinline__ void cpa(unsigned d, const void* s, int valid) {
  int sz = valid ? 16 : 0;
  asm volatile("cp.async.cg.shared.global [%0], [%1], 16, %2;" :: "r"(d), "l"(s), "r"(sz));
}
#define CP_COMMIT asm volatile("cp.async.commit_group;" ::: "memory")
#define CP_WAIT1  asm volatile("cp.async.wait_group 1;" ::: "memory")
#define CP_WAIT0  asm volatile("cp.async.wait_group 0;" ::: "memory")

// ---------------- small linear tile: 32 rows x 64 cols, 128 threads ---------
__device__ __forceinline__ void lin_tile2(const float* __restrict__ A, int a_rpb, size_t a_bs,
    const float* __restrict__ W, const float* __restrict__ bias,
    float* __restrict__ D, int d_rpb, size_t d_bs, int r0, int c0) {
  __shared__ float a_s[32][36];
  __shared__ float b_s[32][68];
  int tid = threadIdx.x;
  int tr = tid & 7, tc = tid >> 3;
  ull acc[4][2];
#pragma unroll
  for (int i = 0; i < 4; i++) { acc[i][0] = 0ull; acc[i][1] = 0ull; }
  float4 pa[2], pw[4];
  int ak[2]; const float* aptr[2];
#pragma unroll
  for (int i = 0; i < 2; i++) {
    int idx = tid + i*128;
    ak[i] = idx & 7;
    int gr = r0 + (idx >> 3);
    aptr[i] = A + (size_t)(gr/a_rpb)*a_bs + (size_t)(gr%a_rpb)*DIM;
    pa[i] = *(const float4*)(aptr[i] + ak[i]*4);
  }
#pragma unroll
  for (int i = 0; i < 4; i++) {
    int idx = tid + i*128;
    pw[i] = *(const float4*)(W + (size_t)(idx>>4)*DIM + c0 + (idx&15)*4);
  }
  for (int t = 0; t < 24; t++) {
#pragma unroll
    for (int i = 0; i < 2; i++) {
      int idx = tid + i*128;
      int r = idx >> 3, kq = idx & 7;
      a_s[kq*4+0][r]=pa[i].x; a_s[kq*4+1][r]=pa[i].y;
      a_s[kq*4+2][r]=pa[i].z; a_s[kq*4+3][r]=pa[i].w;
    }
#pragma unroll
    for (int i = 0; i < 4; i++) {
      int idx = tid + i*128;
      *(float4*)&b_s[idx>>4][(idx&15)*4] = pw[i];
    }
    __syncthreads();
    if (t < 23) {
      int k0 = (t+1)*32;
#pragma unroll
      for (int i = 0; i < 2; i++) pa[i] = *(const float4*)(aptr[i] + k0 + ak[i]*4);
#pragma unroll
      for (int i = 0; i < 4; i++) {
        int idx = tid + i*128;
        pw[i] = *(const float4*)(W + (size_t)(k0 + (idx>>4))*DIM + c0 + (idx&15)*4);
      }
    }
#pragma unroll
    for (int kk = 0; kk < 32; kk++) {
      float4 a4 = *(const float4*)&a_s[kk][tr*4];
      const ull* q0 = (const ull*)&b_s[kk][tc*4];
      ull b0 = q0[0], b1 = q0[1];
      float av[4] = {a4.x, a4.y, a4.z, a4.w};
#pragma unroll
      for (int i = 0; i < 4; i++) {
        ull ai = pk2(av[i]);
        fma2(acc[i][0],ai,b0); fma2(acc[i][1],ai,b1);
      }
    }
    __syncthreads();
  }
#pragma unroll
  for (int i = 0; i < 4; i++) {
    int gr = r0 + tr*4 + i;
    float* dp = D + (size_t)(gr/d_rpb)*d_bs + (size_t)(gr%d_rpb)*DIM;
#pragma unroll
    for (int p = 0; p < 2; p++) {
      float2 v = up2(acc[i][p]);
      int c = c0 + tc*4 + p*2;
      float bb0 = bias ? bias[c]   : 0.f;
      float bb1 = bias ? bias[c+1] : 0.f;
      *(float2*)&dp[c] = make_float2(v.x + bb0, v.y + bb1);
    }
  }
}

// qlin rows 0-7: xmm@fq, 8-11: xmm@qv, 12-15: xmm@qa
__global__ __launch_bounds__(128) void k_qlin3(const float* __restrict__ xmm,
    const float* __restrict__ fq, const float* __restrict__ qv,
    const float* __restrict__ qa) {
  int z = blockIdx.z;
  if (z > 0 && blockIdx.x >= 8) return;
  const float* W = (z==0) ? fq : (z==1 ? qv : qa);
  int off = (z==0) ? 0 : (z==1 ? 8 : 12);
  int rpb = (z==0) ? 8 : 4;
  lin_tile2(xmm + (size_t)off*DIM, rpb, (size_t)16*DIM, W, nullptr,
            g_qlin + (size_t)off*DIM, rpb, (size_t)16*DIM,
            blockIdx.x*32, blockIdx.y*64);
}

// transpose K-halves of kvv_w / kva_w
__global__ __launch_bounds__(256) void k_tr(const float* __restrict__ kvv,
                                            const float* __restrict__ kva) {
  __shared__ float t[32][33];
  const float* src = blockIdx.z ? kva : kvv;
  float* dst = blockIdx.z ? g_kTa : g_kTv;
  int x0 = blockIdx.x*32, y0 = blockIdx.y*32;
  int tx = threadIdx.x & 31, ty = threadIdx.x >> 5;
  for (int i = 0; i < 32; i += 8)
    t[ty+i][tx] = src[(size_t)(y0+ty+i)*2*DIM + x0+tx];
  __syncthreads();
  for (int i = 0; i < 32; i += 8)
    dst[(size_t)(x0+ty+i)*DIM + y0+tx] = t[tx][ty+i];
}

// qtT[b][d][r] = ASCALE * sum_e qlin[b,off+n,h*64+e] * kT[h*64+e][d]
__global__ __launch_bounds__(256) void k_qt3() {
  int h = blockIdx.x, d0 = blockIdx.y*128, tid = threadIdx.x;
  int which = blockIdx.z >> 2, bg = blockIdx.z & 3;
  const float* kT = which ? g_kTa : g_kTv;
  float* qt = which ? g_qt_a : g_qt_v;
  int off = which ? 12 : 8;
  __shared__ float kts[64][129];
  __shared__ float qsh[4][64];
#pragma unroll
  for (int i = 0; i < 8; i++) {
    int idx = tid + i*256;
    int e = idx >> 5, cq = idx & 31;
    float4 v = *(const float4*)(kT + (size_t)(h*64+e)*DIM + d0 + cq*4);
    kts[e][cq*4]=v.x; kts[e][cq*4+1]=v.y; kts[e][cq*4+2]=v.z; kts[e][cq*4+3]=v.w;
  }
  int col = tid & 127, rp = tid >> 7;
  for (int b = bg*16; b < bg*16 + 16; b++) {
    __syncthreads();
    { int n = (tid >> 6) & 3, e = tid & 63;
      qsh[n][e] = g_qlin[((size_t)b*16 + off + n)*DIM + h*64 + e]; }
    __syncthreads();
    float a0 = 0.f, a1 = 0.f;
#pragma unroll
    for (int e = 0; e < 64; e++) {
      float w = kts[e][col];
      a0 += qsh[rp*2][e]*w; a1 += qsh[rp*2+1][e]*w;
    }
    *(float2*)&qt[((size_t)b*DIM + d0 + col)*RQ + h*4 + rp*2] =
        make_float2(a0*ASCALE, a1*ASCALE);
  }
}

// expST[m][r] = exp(X @ qtT) + fused row-sum; 192 thr, m-tile 128,
// per-thread 4m x 8r, xs read via LDS.128 along k, qs warp-broadcast
__global__ __launch_bounds__(192, 4) void k_scores7(const float* __restrict__ xv,
                                                    const float* __restrict__ xa) {
  __shared__ float xs[2][128][36];   // [m][k], pitch 36
  __shared__ float qs[2][32][48];    // [k][r]
  int b = blockIdx.x, y = blockIdx.y, tid = threadIdx.x;
  int which = (y >= 7);
  int m0 = (which ? (y-7) : y) * 128;
  int N2 = which ? 512 : 784;
  const float* X = (which ? xa : xv) + (size_t)b*N2*DIM;
  const float* Q = (which ? g_qt_a : g_qt_v) + (size_t)b*DIM*RQ;
  float* expS = (which ? g_expS_a : g_expS_v) + (size_t)b*N2*RQ;
  float* den  = (which ? g_den_a : g_den_v) + b*RQ;
  int tm = tid & 31, tg = tid >> 5;   // tm: m-lane (4 m's), tg: r-group (8 r's)

  ull acc[4][4];
#pragma unroll
  for (int i = 0; i < 4; i++)
#pragma unroll
    for (int p = 0; p < 4; p++) acc[i][p] = 0ull;

#define LOAD_TILE_S(T, BUF) do {                                            \
    int k0 = (T)*32;                                                        \
_Pragma("unroll")                                                           \
    for (int i = 0; i < 8; i++) {                                           \
      int idx = tid + i*192;                                                \
      if (idx < 1024) {                                                     \
        int m = idx >> 3, c = idx & 7;                                      \
        int ok = (m0+m) < N2;                                               \
        const float* s = X + (size_t)(ok ? (m0+m) : 0)*DIM + k0 + c*4;      \
        cpa(su32(&xs[BUF][m][c*4]), s, ok);                                 \
      } else if (idx < 1408) {                                              \
        int j = idx - 1024;                                                 \
        int kr = j / 12, c = j % 12;                                        \
        cpa(su32(&qs[BUF][kr][c*4]), Q + (size_t)(k0+kr)*RQ + c*4, 1);      \
      }                                                                     \
    }                                                                       \
  } while (0)

  LOAD_TILE_S(0, 0); CP_COMMIT;
  for (int t = 0; t < 24; t++) {
    if (t < 23) { LOAD_TILE_S(t+1, (t+1)&1); CP_COMMIT; CP_WAIT1; }
    else        { CP_WAIT0; }
    __syncthreads();
    int buf = t & 1;
#pragma unroll
    for (int k4 = 0; k4 < 8; k4++) {
      float4 xr[4];
#pragma unroll
      for (int i = 0; i < 4; i++)
        xr[i] = *(const float4*)&xs[buf][tm + 32*i][k4*4];
#pragma unroll
      for (int j = 0; j < 4; j++) {
        const ull* qp = (const ull*)&qs[buf][k4*4+j][tg*8];
        ull b0 = qp[0], b1 = qp[1], b2 = qp[2], b3 = qp[3];
#pragma unroll
        for (int i = 0; i < 4; i++) {
          ull ai = pk2(((const float*)&xr[i])[j]);
          fma2(acc[i][0], ai, b0); fma2(acc[i][1], ai, b1);
          fma2(acc[i][2], ai, b2); fma2(acc[i][3], ai, b3);
        }
      }
    }
    __syncthreads();
  }
#undef LOAD_TILE_S
  // epilogue: exp + store + fused denom partials
  float rs[8] = {0.f,0.f,0.f,0.f,0.f,0.f,0.f,0.f};
#pragma unroll
  for (int i = 0; i < 4; i++) {
    int m = m0 + tm + 32*i;
    if (m < N2) {
      float* row = expS + (size_t)m*RQ + tg*8;
#pragma unroll
      for (int p = 0; p < 4; p++) {
        float2 v = up2(acc[i][p]);
        float e0 = __expf(v.x), e1 = __expf(v.y);
        *(float2*)&row[2*p] = make_float2(e0, e1);
        rs[2*p] += e0; rs[2*p+1] += e1;
      }
    }
  }
  float* red = &qs[0][0][0];   // 48*32 floats, reuse after final barrier
#pragma unroll
  for (int p = 0; p < 8; p++) red[(tg*8+p)*32 + tm] = rs[p];
  __syncthreads();
  if (tid < RQ) {
    float s = 0.f;
#pragma unroll
    for (int j = 0; j < 32; j++) s += red[tid*32 + j];
    atomicAdd(&den[tid], s);
  }
}

// C[r][d] = (expST^T @ X)/den; 192 thr
__global__ __launch_bounds__(192, 4) void k_ctx5(const float* __restrict__ xv,
                                                 const float* __restrict__ xa) {
  __shared__ float es[2][32][48];    // [m][r]
  __shared__ float bs[2][32][132];   // [m][d], pitch 132
  int b = blockIdx.x, d0 = blockIdx.y*128, which = blockIdx.z, tid = threadIdx.x;
  int N2 = which ? 512 : 784;
  const float* E = (which ? g_expS_a : g_expS_v) + (size_t)b*N2*RQ;
  const float* X = (which ? xa : xv) + (size_t)b*N2*DIM;
  const float* den = (which ? g_den_a : g_den_v) + b*RQ;
  float* C = (which ? g_C_a : g_C_v) + (size_t)b*RQ*DIM;
  int tc = tid & 15, tr = tid >> 4;

  ull acc[4][4];
#pragma unroll
  for (int i = 0; i < 4; i++)
#pragma unroll
    for (int p = 0; p < 4; p++) acc[i][p] = 0ull;
  int nt = (N2 + 31) / 32;

#define LOAD_TILE_C(T, BUF) do {                                            \
    int k0 = (T)*32;                                                        \
_Pragma("unroll")                                                           \
    for (int i = 0; i < 8; i++) {                                           \
      int idx = tid + i*192;                                                \
      if (idx < 1024) {                                                     \
        int mm = idx >> 5, c = idx & 31;                                    \
        int ok = (k0+mm) < N2;                                              \
        const float* s = X + (size_t)(ok ? (k0+mm) : 0)*DIM + d0 + c*4;     \
        cpa(su32(&bs[BUF][mm][c*4]), s, ok);                                \
      } else if (idx < 1408) {                                              \
        int j = idx - 1024;                                                 \
        int mm = j / 12, c = j % 12;                                        \
        int ok = (k0+mm) < N2;                                              \
        const float* s = E + (size_t)(ok ? (k0+mm) : 0)*RQ + c*4;           \
        cpa(su32(&es[BUF][mm][c*4]), s, ok);                                \
      }                                                                     \
    }                                                                       \
  } while (0)

  LOAD_TILE_C(0, 0); CP_COMMIT;
  for (int t = 0; t < nt; t++) {
    if (t+1 < nt) { LOAD_TILE_C(t+1, (t+1)&1); CP_COMMIT; CP_WAIT1; }
    else          { CP_WAIT0; }
    __syncthreads();
    int buf = t & 1;
#pragma unroll 8
    for (int mm = 0; mm < 32; mm++) {
      const ull* p0 = (const ull*)&bs[buf][mm][tc*4];
      const ull* p1 = (const ull*)&bs[buf][mm][64 + tc*4];
      ull b0 = p0[0], b1 = p0[1], b2 = p1[0], b3 = p1[1];
      float4 a4 = *(const float4*)&es[buf][mm][tr*4];
      float av[4] = {a4.x, a4.y, a4.z, a4.w};
#pragma unroll
      for (int i = 0; i < 4; i++) {
        ull ai = pk2(av[i]);
        fma2(acc[i][0], ai, b0); fma2(acc[i][1], ai, b1);
        fma2(acc[i][2], ai, b2); fma2(acc[i][3], ai, b3);
      }
    }
    __syncthreads();
  }
#undef LOAD_TILE_C
#pragma unroll
  for (int i = 0; i < 4; i++) {
    int r = tr*4 + i;
    float inv = 1.f / den[r];
    float* crow = C + (size_t)r*DIM + d0;
#pragma unroll
    for (int p = 0; p < 4; p++) {
      float2 v = up2(acc[i][p]);
      int c = (p < 2) ? (tc*4 + 2*p) : (64 + tc*4 + 2*(p-2));
      *(float2*)&crow[c] = make_float2(v.x*inv, v.y*inv);
    }
  }
}

// o = C @ Wv-half (per-head)
__global__ __launch_bounds__(256) void k_ov2(const float* __restrict__ kvv,
                                             const float* __restrict__ kva) {
  int h = blockIdx.x, b0 = blockIdx.y*16, which = blockIdx.z, tid = threadIdx.x;
  const float* C = which ? g_C_a : g_C_v;
  const float* kvw = which ? kva : kvv;
  float* o = which ? g_o_a : g_o_v;
  __shared__ float a_s[32][68];
  __shared__ float b_s[32][68];
  int tr = tid % 16, tc = tid / 16;
  ull acc[4][2];
#pragma unroll
  for (int i = 0; i < 4; i++) { acc[i][0]=0ull; acc[i][1]=0ull; }
  for (int k0 = 0; k0 < DIM; k0 += 32) {
    __syncthreads();
#pragma unroll
    for (int i = 0; i < 2; i++) {
      int idx = tid + i*256;
      int r = idx >> 3, kq = idx & 7;
      const float* ap = C + ((size_t)(b0 + (r>>2))*RQ + h*4 + (r&3))*DIM;
      float4 v = *(const float4*)(ap + k0 + kq*4);
      a_s[kq*4+0][r]=v.x; a_s[kq*4+1][r]=v.y; a_s[kq*4+2][r]=v.z; a_s[kq*4+3][r]=v.w;
    }
#pragma unroll
    for (int i = 0; i < 2; i++) {
      int idx = tid + i*256;
      int k = idx >> 4, cq = idx & 15;
      float4 v = *(const float4*)(kvw + (size_t)(k0+k)*2*DIM + DIM + h*64 + cq*4);
      *(float4*)&b_s[k][cq*4] = v;
    }
    __syncthreads();
#pragma unroll
    for (int kk = 0; kk < 32; kk++) {
      float4 a4 = *(const float4*)&a_s[kk][tr*4];
      const ull* q0 = (const ull*)&b_s[kk][tc*4];
      ull bp0 = q0[0], bp1 = q0[1];
      float av[4] = {a4.x, a4.y, a4.z, a4.w};
#pragma unroll
      for (int i = 0; i < 4; i++) {
        ull ai = pk2(av[i]);
        fma2(acc[i][0],ai,bp0); fma2(acc[i][1],ai,bp1);
      }
    }
  }
#pragma unroll
  for (int i = 0; i < 4; i++) {
    int r = tr*4 + i;
    float* dp = o + ((size_t)(b0 + (r>>2))*4 + (r&3))*DIM + h*64;
#pragma unroll
    for (int p = 0; p < 2; p++) {
      float2 v = up2(acc[i][p]);
      int c = tc*4 + p*2;
      dp[c] = v.x; dp[c+1] = v.y;
    }
  }
}

__global__ __launch_bounds__(128) void k_lin_proj3(const float* __restrict__ pv_w,
    const float* __restrict__ pv_b, const float* __restrict__ pa_w,
    const float* __restrict__ pa_b, float* __restrict__ out) {
  int z = blockIdx.z;
  lin_tile2(z ? g_o_a : g_o_v, 4, (size_t)4*DIM, z ? pa_w : pv_w, z ? pa_b : pv_b,
            out + (size_t)(8 + 4*z)*DIM, 4, (size_t)16*DIM,
            blockIdx.x*32, blockIdx.y*64);
}

__global__ __launch_bounds__(128) void k_lin_kv3(const float* __restrict__ fk,
    const float* __restrict__ fv, const float* __restrict__ out) {
  int z = blockIdx.z, half = z & 1;
  const float* W = (z < 2 ? fk : fv) + (size_t)half*DIM*DIM;
  float* D = (z==0) ? g_kfv : (z==1) ? g_kfa : (z==2) ? g_vfv : g_vfa;
  lin_tile2(out + (size_t)(8 + 4*half)*DIM, 4, (size_t)16*DIM, W, nullptr,
            D, 4, (size_t)4*DIM, blockIdx.x*32, blockIdx.y*64);
}

__global__ __launch_bounds__(128) void k_lin_fproj3(const float* __restrict__ W,
    const float* __restrict__ bias, float* __restrict__ out) {
  lin_tile2(g_of, 8, (size_t)8*DIM, W, bias, out, 8, (size_t)16*DIM,
            blockIdx.x*32, blockIdx.y*64);
}

// final 8x16 attention, one head per block
__global__ __launch_bounds__(128) void k_fused2(float* __restrict__ out, int wattn) {
  int b = blockIdx.x, h = blockIdx.y, tid = threadIdx.x;
  float* attn = wattn ? (out + (size_t)BATCH*16*DIM) : g_attn;
  __shared__ float qh[8][64], kh[16][64], vh[16][64], ps[8][16];
  int n_s = tid >> 4, t_s = tid & 15;
  for (int i = tid; i < 512; i += 128) {
    int n = i >> 6, e = i & 63;
    qh[n][e] = g_qlin[((size_t)b*16 + n)*DIM + h*64 + e];
  }
  for (int i = tid; i < 1024; i += 128) {
    int t = i >> 6, e = i & 63;
    kh[t][e] = g_kfv[((size_t)b*4 + (t>>2))*DIM + h*64 + e]
             + g_kfa[((size_t)b*4 + (t&3))*DIM + h*64 + e];
    vh[t][e] = g_vfv[((size_t)b*4 + (t>>2))*DIM + h*64 + e]
             + g_vfa[((size_t)b*4 + (t&3))*DIM + h*64 + e];
  }
  __syncthreads();
  float sc = 0.f;
#pragma unroll 8
  for (int e = 0; e < 64; e++) sc += qh[n_s][e]*kh[t_s][e];
  sc *= ASCALE;
  float mx = sc;
#pragma unroll
  for (int o = 8; o; o >>= 1) mx = fmaxf(mx, __shfl_xor_sync(0xffffffffu, mx, o));
  float ex = expf(sc - mx), sm = ex;
#pragma unroll
  for (int o = 8; o; o >>= 1) sm += __shfl_xor_sync(0xffffffffu, sm, o);
  float p = ex/sm;
  attn[(((size_t)b*NH + h)*8 + n_s)*16 + t_s] = p;
  ps[n_s][t_s] = p;
  __syncthreads();
  for (int i = tid; i < 512; i += 128) {
    int n = i >> 6, e = i & 63;
    float acc = 0.f;
#pragma unroll
    for (int t = 0; t < 16; t++) acc += ps[n][t]*vh[t][e];
    g_of[((size_t)b*8 + n)*DIM + h*64 + e] = acc;
  }
}

extern "C" void kernel_launch(void* const* d_in, const int* in_sizes, int n_in,
                              void* d_out, int out_size) {
  const float* xmm    = (const float*)d_in[0];
  const float* xv     = (const float*)d_in[1];
  const float* xa     = (const float*)d_in[2];
  const float* qv_w   = (const float*)d_in[3];
  const float* kvv_w  = (const float*)d_in[4];
  const float* projv_w= (const float*)d_in[5];
  const float* projv_b= (const float*)d_in[6];
  const float* qa_w   = (const float*)d_in[7];
  const float* kva_w  = (const float*)d_in[8];
  const float* proja_w= (const float*)d_in[9];
  const float* proja_b= (const float*)d_in[10];
  const float* fq_w   = (const float*)d_in[11];
  const float* fk_w   = (const float*)d_in[12];
  const float* fv_w   = (const float*)d_in[13];
  const float* fproj_w= (const float*)d_in[14];
  const float* fproj_b= (const float*)d_in[15];
  float* out = (float*)d_out;
  int wattn = (out_size >= BATCH*16*DIM + BATCH*NH*8*16) ? 1 : 0;

  void *p_denv, *p_dena;
  cudaGetSymbolAddress(&p_denv, g_den_v);
  cudaGetSymbolAddress(&p_dena, g_den_a);
  cudaMemsetAsync(p_denv, 0, BATCH*RQ*sizeof(float));
  cudaMemsetAsync(p_dena, 0, BATCH*RQ*sizeof(float));

  k_qlin3<<<dim3(16,12,3), 128>>>(xmm, fq_w, qv_w, qa_w);
  k_tr<<<dim3(24,24,2), 256>>>(kvv_w, kva_w);
  k_qt3<<<dim3(12,6,8), 256>>>();
  k_scores7<<<dim3(64,11), 192>>>(xv, xa);
  k_ctx5<<<dim3(64,6,2), 192>>>(xv, xa);
  k_ov2<<<dim3(12,4,2), 256>>>(kvv_w, kva_w);
  k_lin_proj3<<<dim3(8,12,2), 128>>>(projv_w, projv_b, proja_w, proja_b, out);
  k_lin_kv3<<<dim3(8,12,4), 128>>>(fk_w, fv_w, out);
  k_fused2<<<dim3(64,12), 128>>>(out, wattn);
  k_lin_fproj3<<<dim3(16,12), 128>>>(fproj_w, fproj_b, out);
}